// round 15
// baseline (speedup 1.0000x reference)
#include <cuda_runtime.h>
#include <cuda_fp16.h>
#include <math.h>
#include <stdint.h>

constexpr int Bb = 512, Tt = 128, Dd = 128, Hh = 512, MEMN = 64;
constexpr int NCTA = 128, NTHR = 256;
constexpr int LD1 = 648, LD2 = 520;          // weight smem row strides (elems, 16B-aligned)
constexpr int SO_W1 = 0;
constexpr int SO_W2 = 96 * LD1 * 2;          // 124416
constexpr int SO_STG = SO_W2 + 80 * LD2 * 2; // 207616
constexpr int STG_BYTES = 128 * 64;          // 8192 per stage (128 rows x 64B, swizzled)
constexpr int SM_RECUR = SO_STG + 3 * STG_BYTES;  // 232192
constexpr int KCAT = 1152;                   // [h 512 | e 512 | x 128]

// ---------------- device scratch ----------------
__device__ __half g_hB[Bb * Hh];                      // h, [b][512]
__device__ __half g_sB[Bb * Hh];                      // s_t, [b][512]
__device__ __half g_Xh[(size_t)Tt * Bb * Dd];         // x, [t][b][128]
__device__ float  g_dtT[Tt * Bb];                     // dt, [t][b]
__device__ __half g_histB[(size_t)MEMN * Bb * Hh];    // [m][b][h]
__device__ __half g_qh[Bb * 2 * Hh];                  // [b][ h | c ]
__device__ __half g_cat[Bb * KCAT];                   // [b][ h | e | x_last ]
__device__ unsigned g_cnt4[128];                      // 4 group counters, 128B apart
__device__ unsigned g_qwdone;
// tail scratch
__device__ __half g_WahT[Hh * Hh];
__device__ __half g_WaqT[Hh * 2 * Hh];
__device__ __half g_WcatT[Hh * KCAT];                 // [n][ W_h k | We k | Wg k ]
__device__ float g_qWf[Bb * Hh];
__device__ float g_hfin[Bb * Hh];
__device__ float g_scores[Bb * MEMN];
__device__ float g_dot[Bb];

// ---------------- helpers ----------------
__device__ __forceinline__ float sigmoidf_(float x) { return 1.f / (1.f + expf(-x)); }

__device__ __forceinline__ uint32_t packh2(float lo, float hi) {
    uint32_t r;
    asm("cvt.rn.f16x2.f32 %0, %1, %2;" : "=r"(r) : "f"(hi), "f"(lo));
    return r;
}
__device__ __forceinline__ uint32_t smem_u32(const void* p) {
    uint32_t a;
    asm("{ .reg .u64 t; cvta.to.shared.u64 t, %1; cvt.u32.u64 %0, t; }" : "=r"(a) : "l"(p));
    return a;
}
__device__ __forceinline__ void cp16b(uint32_t dst, const __half* src) {
    asm volatile("cp.async.cg.shared.global [%0], [%1], 16;" :: "r"(dst), "l"(src));
}
__device__ __forceinline__ void cp16s(__half* dst_smem, const __half* src) {
    uint32_t d = (uint32_t)__cvta_generic_to_shared(dst_smem);
    asm volatile("cp.async.cg.shared.global [%0], [%1], 16;" :: "r"(d), "l"(src));
}
__device__ __forceinline__ void cp_commit() { asm volatile("cp.async.commit_group;"); }
template <int N>
__device__ __forceinline__ void cp_wait() { asm volatile("cp.async.wait_group %0;" :: "n"(N)); }

__device__ __forceinline__ void ldsm4(uint32_t* r, uint32_t a) {
    asm volatile("ldmatrix.sync.aligned.m8n8.x4.shared.b16 {%0,%1,%2,%3}, [%4];"
                 : "=r"(r[0]), "=r"(r[1]), "=r"(r[2]), "=r"(r[3]) : "r"(a));
}
__device__ __forceinline__ void ldsm2(uint32_t* r, uint32_t a) {
    asm volatile("ldmatrix.sync.aligned.m8n8.x2.shared.b16 {%0,%1}, [%2];"
                 : "=r"(r[0]), "=r"(r[1]) : "r"(a));
}
__device__ __forceinline__ uint32_t ldu32(const __half* p) {
    return *reinterpret_cast<const uint32_t*>(p);
}
// f16 accumulate (2 regs)
__device__ __forceinline__ void mma16816h(uint32_t* c, uint32_t a0, uint32_t a1,
                                          uint32_t a2, uint32_t a3, uint32_t b0, uint32_t b1) {
    asm volatile(
        "mma.sync.aligned.m16n8k16.row.col.f16.f16.f16.f16 "
        "{%0,%1}, {%2,%3,%4,%5}, {%6,%7}, {%0,%1};"
        : "+r"(c[0]), "+r"(c[1])
        : "r"(a0), "r"(a1), "r"(a2), "r"(a3), "r"(b0), "r"(b1));
}
// per-group grid barrier (32 CTAs sharing the same mi)
__device__ __forceinline__ void gridbar_g(unsigned* cnt, unsigned target) {
    __syncthreads();
    if (threadIdx.x == 0) {
        __threadfence();
        atomicAdd(cnt, 1u);
        unsigned v;
        do {
            asm volatile("ld.acquire.gpu.u32 %0, [%1];" : "=r"(v) : "l"(cnt) : "memory");
        } while (v < target);
    }
    __syncthreads();
}

// ---------------- init ----------------
__global__ void k_init(const float* __restrict__ X) {
    int idx = blockIdx.x * 256 + threadIdx.x;
    if (idx == 0) g_qwdone = 0u;
    if (idx < 128) g_cnt4[idx] = 0u;
    if (idx < Bb) g_dot[idx] = 0.f;
    if (idx < Bb * MEMN) g_scores[idx] = 0.f;
    if (idx < Bb * Hh) { g_qWf[idx] = 0.f; g_hfin[idx] = 0.f; }
    if (idx < Bb * Hh / 2) reinterpret_cast<uint32_t*>(g_hB)[idx] = 0u;
    if (idx < Tt * Bb) {
        int t = idx >> 9, b = idx & 511;
        g_dtT[idx] = X[((size_t)b * Tt + t) * (Dd + 1) + Dd];
    }
    if (idx < Bb * Dd) {
        int b = idx >> 7, d = idx & 127;
        g_cat[(size_t)b * KCAT + 1024 + d] =
            __float2half(X[((size_t)b * Tt + (Tt - 1)) * (Dd + 1) + d]);
    }
    if (idx < Tt * Bb * (Dd / 2)) {
        int dp = idx & 63, rem = idx >> 6;
        int b = rem & 511, t = rem >> 9;
        const float* xp = X + ((size_t)b * Tt + t) * (Dd + 1) + 2 * dp;
        reinterpret_cast<uint32_t*>(g_Xh)[idx] = packh2(xp[0], xp[1]);
    }
}

// ---------------- merged weight transpose/pack (tail) ----------------
__global__ void k_packAll(const float* __restrict__ Wah, const float* __restrict__ Waq,
                          const float* __restrict__ W_h, const float* __restrict__ We,
                          const float* __restrict__ Wg) {
    int idx = blockIdx.x * 256 + threadIdx.x;
    if (idx < 262144) {
        int n = idx >> 9, k = idx & 511;
        g_WahT[idx] = __float2half(Wah[(size_t)k * 512 + n]);
    } else if (idx < 786432) {
        int j = idx - 262144; int n = j >> 10, k = j & 1023;
        g_WaqT[j] = __float2half(Waq[(size_t)k * 512 + n]);
    } else if (idx < 1376256) {
        int j = idx - 786432;
        int n = j / KCAT, k = j - n * KCAT;
        float v;
        if (k < 512)       v = W_h[(size_t)k * 512 + n];
        else if (k < 1024) v = We[(size_t)(k - 512) * 512 + n];
        else               v = Wg[(size_t)(k - 1024) * 512 + n];
        g_WcatT[j] = __float2half(v);
    }
}

// ---------------- persistent recurrent kernel ----------------
__global__ void __launch_bounds__(NTHR, 1)
k_recur(const float* __restrict__ Wh, const float* __restrict__ Wx,
        const float* __restrict__ Wst, const float* __restrict__ Ws,
        const float* __restrict__ bh_lin, const float* __restrict__ bx_lin,
        const float* __restrict__ bg, const float* __restrict__ bst,
        const float* __restrict__ bs_lin) {
    extern __shared__ __align__(16) __half sm[];
    const uint32_t sbase = smem_u32(sm);
    const uint32_t w1u = sbase + SO_W1, w2u = sbase + SO_W2, stgu = sbase + SO_STG;
    __half* w1s = sm;
    __half* w2s = sm + 96 * LD1;

    const int tid = threadIdx.x, cta = blockIdx.x;
    const int w = tid >> 5, lane = tid & 31;
    const int lq = lane >> 2, lr = lane & 3;
    const int wm = w >> 1, wn = w & 1;
    const int mi = cta & 3, hi = cta >> 2;
    const int m0 = mi * 128, hh0 = hi * 16;
    unsigned* cnt = &g_cnt4[mi * 32];

    for (int idx = tid; idx < 96 * 640; idx += NTHR) {
        int n = idx / 640, k = idx - n * 640;
        int wn_ = n / 48, rem = n - wn_ * 48, jn = rem >> 3, c = rem & 7;
        int g = (jn < 5) ? jn + 1 : 0;
        int hh = hh0 + wn_ * 8 + c;
        float v = (k < 512) ? Wh[((size_t)(g * 512 + k)) * 512 + hh]
                            : Wx[((size_t)(g * 128 + (k - 512))) * 512 + hh];
        w1s[n * LD1 + k] = __float2half(v);
    }
    for (int idx = tid; idx < 80 * 512; idx += NTHR) {
        int n = idx >> 9, k = idx & 511;
        int wn_ = n / 40, rem = n - wn_ * 40, jn = rem >> 3, c = rem & 7;
        int hh = hh0 + wn_ * 8 + c;
        w2s[n * LD2 + k] = __float2half(Ws[((size_t)(jn * 512 + k)) * 512 + hh]);
    }
    __syncthreads();

    const int hhp = hh0 + wn * 8 + lr * 2;
    float biasG[5][2], bias0[2], wstv[2];
#pragma unroll
    for (int e = 0; e < 2; e++) {
        int hh = hhp + e;
        bias0[e] = bh_lin[hh] + bx_lin[hh] + bg[hh] + bst[hh];
        wstv[e] = Wst[hh];
#pragma unroll
        for (int q = 0; q < 5; q++) {
            int gc = (q + 1) * 512 + hh;
            biasG[q][e] = bh_lin[gc] + bx_lin[gc] + bg[gc] + bs_lin[q * 512 + hh];
        }
    }

    const int hi4 = (lane >> 4) & 1;
    uint32_t rowA[2], swzA[2];
#pragma unroll
    for (int im = 0; im < 2; im++) {
        int R = wm * 32 + im * 16 + (lane & 15);
        rowA[im] = (uint32_t)R * 64u;
        swzA[im] = (uint32_t)((R >> 1) & 3);
    }
    uint32_t boff1[3];
#pragma unroll
    for (int p = 0; p < 3; p++) {
        int n = wn * 48 + p * 16 + (lane & 7) + ((lane & 16) >> 1);
        boff1[p] = (uint32_t)n * (LD1 * 2) + ((lane & 8) << 1);
    }
    uint32_t boff2[2], boff2x;
#pragma unroll
    for (int p = 0; p < 2; p++) {
        int n = wn * 40 + p * 16 + (lane & 7) + ((lane & 16) >> 1);
        boff2[p] = (uint32_t)n * (LD2 * 2) + ((lane & 8) << 1);
    }
    {
        int n = wn * 40 + 32 + (lane & 7);
        boff2x = (uint32_t)n * (LD2 * 2) + ((lane & 8) << 1);
    }
    const int str = tid >> 1, ss0 = (tid & 1) * 2;
    const uint32_t swr = (uint32_t)((str >> 1) & 3);
    const uint32_t wdst0 = (uint32_t)str * 64u + (((uint32_t)ss0 ^ swr) & 3u) * 16u;
    const uint32_t wdst1 = (uint32_t)str * 64u + (((uint32_t)(ss0 + 1) ^ swr) & 3u) * 16u;

    float c_reg[2][2][2], s_reg[2][2][2];
#pragma unroll
    for (int i = 0; i < 2; i++)
#pragma unroll
        for (int j = 0; j < 2; j++) { c_reg[i][j][0] = 0.f; c_reg[i][j][1] = 0.f; }

    unsigned bar = 0;

    for (int t = 0; t < Tt; t++) {
        uint32_t acc[12][2];
#pragma unroll
        for (int j = 0; j < 12; j++) { acc[j][0] = 0u; acc[j][1] = 0u; }

        // ===== phase 1: [h | x_t] @ W1, K=640, 20 chunks, 3-stage (2 in flight) =====
        {
            const __half* hrow = g_hB + (size_t)(m0 + str) * 512 + ss0 * 8;
            const __half* xrow = g_Xh + ((size_t)t * 512 + m0 + str) * 128 + ss0 * 8;
#pragma unroll
            for (int pc = 0; pc < 2; pc++) {
                const __half* src = hrow + pc * 32;
                cp16b(stgu + pc * STG_BYTES + wdst0, src);
                cp16b(stgu + pc * STG_BYTES + wdst1, src + 8);
                cp_commit();
            }
            int st = 0;
            for (int ch = 0; ch < 20; ch++) {
                if (ch + 2 < 20) {
                    int c2 = ch + 2;
                    int s2 = st + 2; if (s2 >= 3) s2 -= 3;
                    const __half* src = (c2 < 16) ? hrow + c2 * 32 : xrow + (c2 - 16) * 32;
                    cp16b(stgu + s2 * STG_BYTES + wdst0, src);
                    cp16b(stgu + s2 * STG_BYTES + wdst1, src + 8);
                    cp_commit();
                    cp_wait<2>();
                } else if (ch + 2 == 20) cp_wait<1>();
                else cp_wait<0>();
                __syncthreads();
                const uint32_t abuf = stgu + st * STG_BYTES;
                const uint32_t kb = (uint32_t)ch * 64u;
#pragma unroll
                for (int half = 0; half < 2; half++) {
                    uint32_t A0[4], A1[4], Bv[12];
                    uint32_t sseg = (uint32_t)(half * 2 + hi4);
                    ldsm4(A0, abuf + rowA[0] + ((sseg ^ swzA[0]) & 3u) * 16u);
                    ldsm4(A1, abuf + rowA[1] + ((sseg ^ swzA[1]) & 3u) * 16u);
                    uint32_t kw = kb + (uint32_t)half * 32u;
                    ldsm4(Bv + 0, w1u + boff1[0] + kw);
                    ldsm4(Bv + 4, w1u + boff1[1] + kw);
                    ldsm4(Bv + 8, w1u + boff1[2] + kw);
#pragma unroll
                    for (int jn = 0; jn < 6; jn++) {
                        mma16816h(acc[jn],     A0[0], A0[1], A0[2], A0[3], Bv[2 * jn], Bv[2 * jn + 1]);
                        mma16816h(acc[6 + jn], A1[0], A1[1], A1[2], A1[3], Bv[2 * jn], Bv[2 * jn + 1]);
                    }
                }
                if (++st == 3) st = 0;
            }
        }
#pragma unroll
        for (int im = 0; im < 2; im++)
#pragma unroll
            for (int hf = 0; hf < 2; hf++) {
                int b = m0 + wm * 32 + im * 16 + lq + hf * 8;
                float dt = g_dtT[t * 512 + b];
                float2 pv = __half22float2(*reinterpret_cast<__half2*>(&acc[im * 6 + 5][hf]));
                float s0 = tanhf(pv.x + bias0[0] + dt * wstv[0]);
                float s1 = tanhf(pv.y + bias0[1] + dt * wstv[1]);
                s_reg[im][hf][0] = s0; s_reg[im][hf][1] = s1;
                *reinterpret_cast<uint32_t*>(&g_sB[(size_t)b * 512 + hhp]) = packh2(s0, s1);
            }
        bar += 32; gridbar_g(cnt, bar);

        // ===== phase 2: s @ Ws accumulates onto acc gates, K=512, 16 chunks =====
        {
            const __half* srow = g_sB + (size_t)(m0 + str) * 512 + ss0 * 8;
#pragma unroll
            for (int pc = 0; pc < 2; pc++) {
                const __half* src = srow + pc * 32;
                cp16b(stgu + pc * STG_BYTES + wdst0, src);
                cp16b(stgu + pc * STG_BYTES + wdst1, src + 8);
                cp_commit();
            }
            int st = 0;
            for (int ch = 0; ch < 16; ch++) {
                if (ch + 2 < 16) {
                    int s2 = st + 2; if (s2 >= 3) s2 -= 3;
                    const __half* src = srow + (ch + 2) * 32;
                    cp16b(stgu + s2 * STG_BYTES + wdst0, src);
                    cp16b(stgu + s2 * STG_BYTES + wdst1, src + 8);
                    cp_commit();
                    cp_wait<2>();
                } else if (ch + 2 == 16) cp_wait<1>();
                else cp_wait<0>();
                __syncthreads();
                const uint32_t abuf = stgu + st * STG_BYTES;
                const uint32_t kb = (uint32_t)ch * 64u;
#pragma unroll
                for (int half = 0; half < 2; half++) {
                    uint32_t A0[4], A1[4], Bv[10];
                    uint32_t sseg = (uint32_t)(half * 2 + hi4);
                    ldsm4(A0, abuf + rowA[0] + ((sseg ^ swzA[0]) & 3u) * 16u);
                    ldsm4(A1, abuf + rowA[1] + ((sseg ^ swzA[1]) & 3u) * 16u);
                    uint32_t kw = kb + (uint32_t)half * 32u;
                    ldsm4(Bv + 0, w2u + boff2[0] + kw);
                    ldsm4(Bv + 4, w2u + boff2[1] + kw);
                    ldsm2(Bv + 8, w2u + boff2x + kw);
#pragma unroll
                    for (int jn = 0; jn < 5; jn++) {
                        mma16816h(acc[jn],     A0[0], A0[1], A0[2], A0[3], Bv[2 * jn], Bv[2 * jn + 1]);
                        mma16816h(acc[6 + jn], A1[0], A1[1], A1[2], A1[3], Bv[2 * jn], Bv[2 * jn + 1]);
                    }
                }
                if (++st == 3) st = 0;
            }
        }
#pragma unroll
        for (int im = 0; im < 2; im++)
#pragma unroll
            for (int hf = 0; hf < 2; hf++) {
                int b = m0 + wm * 32 + im * 16 + lq + hf * 8;
                float2 gv[5];
#pragma unroll
                for (int q = 0; q < 5; q++)
                    gv[q] = __half22float2(*reinterpret_cast<__half2*>(&acc[im * 6 + q][hf]));
                float h2[2];
#pragma unroll
                for (int e = 0; e < 2; e++) {
                    float p0 = e ? gv[0].y : gv[0].x;
                    float p1 = e ? gv[1].y : gv[1].x;
                    float p2 = e ? gv[2].y : gv[2].x;
                    float p3 = e ? gv[3].y : gv[3].x;
                    float p4 = e ? gv[4].y : gv[4].x;
                    float f  = sigmoidf_(p0 + biasG[0][e]);
                    float i_ = sigmoidf_(p1 + biasG[1][e]);
                    float Tg = sigmoidf_(p2 + biasG[2][e]);
                    float z  = tanhf(p3 + biasG[3][e]);
                    float o  = sigmoidf_(p4 + biasG[4][e]);
                    float cn = f * c_reg[im][hf][e] + i_ * z + Tg * s_reg[im][hf][e];
                    c_reg[im][hf][e] = cn;
                    h2[e] = o * tanhf(cn);
                }
                uint32_t hp2 = packh2(h2[0], h2[1]);
                *reinterpret_cast<uint32_t*>(&g_hB[(size_t)b * 512 + hhp]) = hp2;
                if (t >= Tt - MEMN)
                    *reinterpret_cast<uint32_t*>(
                        &g_histB[(size_t)(t - (Tt - MEMN)) * (Bb * Hh) + (size_t)b * 512 + hhp]) = hp2;
                if (t == Tt - 1) {
                    *reinterpret_cast<uint32_t*>(&g_qh[(size_t)b * 1024 + hhp]) = hp2;
                    *reinterpret_cast<uint32_t*>(&g_qh[(size_t)b * 1024 + 512 + hhp]) =
                        packh2(c_reg[im][hf][0], c_reg[im][hf][1]);
                    *reinterpret_cast<uint32_t*>(&g_cat[(size_t)b * KCAT + hhp]) = hp2;
                }
            }
        bar += 32; gridbar_g(cnt, bar);
    }
}

// ---------------- tail GEMM: qW slices | hsW+scores | cat h/x slices -> hfin ----------------
__global__ void __launch_bounds__(256) k_tail1(const float* __restrict__ baq,
                                               const float* __restrict__ bah,
                                               const float* __restrict__ vt) {
    __shared__ __half as[2][128 * 40];
    __shared__ __half bs[2][128 * 40];
    const int tid = threadIdx.x, w = tid >> 5, lane = tid & 31;
    const int lq = lane >> 2, lr = lane & 3;
    const int wm = w >> 1, wn = w & 1;
    const int col0 = blockIdx.x * 128;

    // mode: 0 = qW slice, 1 = hsW+scores, 2 = cat slice -> hfin
    int mode;
    const __half* A; const __half* Bt; int row0, nch, aStr, bStr; size_t kOff;
    if (blockIdx.y < 16) {
        mode = 0;
        int qi = blockIdx.y;
        row0 = (qi & 3) * 128;
        kOff = (size_t)(qi >> 2) * 256;
        A = g_qh; Bt = g_WaqT; aStr = 1024; bStr = 1024; nch = 8;
    } else if (blockIdx.y < 272) {
        mode = 1;
        row0 = (blockIdx.y - 16) * 128;
        kOff = 0;
        A = g_histB; Bt = g_WahT; aStr = 512; bStr = 512; nch = 16;
    } else if (blockIdx.y < 276) {
        mode = 2;   // cat h-slice
        row0 = (blockIdx.y - 272) * 128;
        kOff = 0;
        A = g_cat; Bt = g_WcatT; aStr = KCAT; bStr = KCAT; nch = 16;
    } else {
        mode = 2;   // cat x-slice
        row0 = (blockIdx.y - 276) * 128;
        kOff = 1024;
        A = g_cat; Bt = g_WcatT; aStr = KCAT; bStr = KCAT; nch = 4;
    }

    uint32_t acc[2][8][2];
#pragma unroll
    for (int i = 0; i < 2; i++)
#pragma unroll
        for (int j = 0; j < 8; j++) { acc[i][j][0] = 0u; acc[i][j][1] = 0u; }

    const int r = tid >> 1, part = (tid & 1) * 16;
    const __half* sa0 = A + (size_t)(row0 + r) * aStr + kOff + part;
    const __half* sb0 = Bt + (size_t)(col0 + r) * bStr + kOff + part;
    {
        cp16s(&as[0][r * 40 + part], sa0); cp16s(&as[0][r * 40 + part + 8], sa0 + 8);
        cp16s(&bs[0][r * 40 + part], sb0); cp16s(&bs[0][r * 40 + part + 8], sb0 + 8);
        cp_commit();
    }
    for (int ch = 0; ch < nch; ch++) {
        if (ch < nch - 1) {
            int buf = (ch + 1) & 1;
            const __half* sa = sa0 + (ch + 1) * 32;
            const __half* sb = sb0 + (ch + 1) * 32;
            cp16s(&as[buf][r * 40 + part], sa); cp16s(&as[buf][r * 40 + part + 8], sa + 8);
            cp16s(&bs[buf][r * 40 + part], sb); cp16s(&bs[buf][r * 40 + part + 8], sb + 8);
            cp_commit(); cp_wait<1>();
        } else cp_wait<0>();
        __syncthreads();
        const __half* ab = as[ch & 1];
        const __half* bb2 = bs[ch & 1];
#pragma unroll
        for (int hf2 = 0; hf2 < 2; hf2++) {
            const int kk = hf2 * 16;
            uint32_t ar[2][4];
#pragma unroll
            for (int im = 0; im < 2; im++) {
                const __half* ap = ab + (wm * 32 + im * 16 + lq) * 40 + kk + lr * 2;
                ar[im][0] = ldu32(ap); ar[im][1] = ldu32(ap + 8 * 40);
                ar[im][2] = ldu32(ap + 8); ar[im][3] = ldu32(ap + 8 * 40 + 8);
            }
#pragma unroll
            for (int jn = 0; jn < 8; jn++) {
                const __half* bp = bb2 + (wn * 64 + jn * 8 + lq) * 40 + kk + lr * 2;
                uint32_t b0 = ldu32(bp), b1 = ldu32(bp + 8);
                mma16816h(acc[0][jn], ar[0][0], ar[0][1], ar[0][2], ar[0][3], b0, b1);
                mma16816h(acc[1][jn], ar[1][0], ar[1][1], ar[1][2], ar[1][3], b0, b1);
            }
        }
        __syncthreads();
    }

    if (mode == 0) {
#pragma unroll
        for (int im = 0; im < 2; im++)
#pragma unroll
            for (int jn = 0; jn < 8; jn++)
#pragma unroll
                for (int hf = 0; hf < 2; hf++) {
                    int row = row0 + wm * 32 + im * 16 + lq + hf * 8;
                    int col = col0 + wn * 64 + jn * 8 + lr * 2;
                    float2 v = __half22float2(*reinterpret_cast<__half2*>(&acc[im][jn][hf]));
                    atomicAdd(&g_qWf[(size_t)row * 512 + col], v.x);
                    atomicAdd(&g_qWf[(size_t)row * 512 + col + 1], v.y);
                }
        __threadfence();
        __syncthreads();
        if (tid == 0) atomicAdd(&g_qwdone, 1u);
    } else if (mode == 2) {
#pragma unroll
        for (int im = 0; im < 2; im++)
#pragma unroll
            for (int jn = 0; jn < 8; jn++)
#pragma unroll
                for (int hf = 0; hf < 2; hf++) {
                    int row = row0 + wm * 32 + im * 16 + lq + hf * 8;
                    int col = col0 + wn * 64 + jn * 8 + lr * 2;
                    float2 v = __half22float2(*reinterpret_cast<__half2*>(&acc[im][jn][hf]));
                    atomicAdd(&g_hfin[(size_t)row * 512 + col], v.x);
                    atomicAdd(&g_hfin[(size_t)row * 512 + col + 1], v.y);
                }
    } else {
        // fused scores epilogue: needs qW complete (64 producer CTAs, all in wave 1)
        float bv[8][2], vv[8][2];
#pragma unroll
        for (int jn = 0; jn < 8; jn++)
#pragma unroll
            for (int e = 0; e < 2; e++) {
                int col = col0 + wn * 64 + jn * 8 + lr * 2 + e;
                bv[jn][e] = baq[col] + bah[col];
                vv[jn][e] = vt[col];
            }
        if (tid == 0) {
            unsigned v;
            do {
                asm volatile("ld.acquire.gpu.u32 %0, [%1];" : "=r"(v) : "l"(&g_qwdone) : "memory");
            } while (v < 64u);
        }
        __syncthreads();
#pragma unroll
        for (int im = 0; im < 2; im++)
#pragma unroll
            for (int hf = 0; hf < 2; hf++) {
                int row = row0 + wm * 32 + im * 16 + lq + hf * 8;
                int b = row & 511, m = row >> 9;
                float rs = 0.f;
#pragma unroll
                for (int jn = 0; jn < 8; jn++) {
                    int col = col0 + wn * 64 + jn * 8 + lr * 2;
                    float2 hv = __half22float2(*reinterpret_cast<__half2*>(&acc[im][jn][hf]));
                    float q0 = g_qWf[(size_t)b * 512 + col];
                    float q1 = g_qWf[(size_t)b * 512 + col + 1];
                    rs += tanhf(hv.x + q0 + bv[jn][0]) * vv[jn][0];
                    rs += tanhf(hv.y + q1 + bv[jn][1]) * vv[jn][1];
                }
                rs += __shfl_xor_sync(0xffffffffu, rs, 1);
                rs += __shfl_xor_sync(0xffffffffu, rs, 2);
                if (lr == 0) atomicAdd(&g_scores[b * MEMN + m], rs);
            }
    }
}

// ---------------- cat GEMM e-slice (K=512) with fused tanh->Wc dot epilogue ----------------
__global__ void __launch_bounds__(256) k_catdot(const float* __restrict__ b_Wh,
                                                const float* __restrict__ b_We,
                                                const float* __restrict__ b_Wg,
                                                const float* __restrict__ bh_p,
                                                const float* __restrict__ Wc) {
    __shared__ __half as[2][128 * 40];
    __shared__ __half bs[2][128 * 40];
    const int tid = threadIdx.x, w = tid >> 5, lane = tid & 31;
    const int lq = lane >> 2, lr = lane & 3;
    const int row0 = blockIdx.y * 128, col0 = blockIdx.x * 128;
    const int wm = w >> 1, wn = w & 1;
    const int nch = 16;   // e-slice K=512

    uint32_t acc[2][8][2];
#pragma unroll
    for (int i = 0; i < 2; i++)
#pragma unroll
        for (int j = 0; j < 8; j++) { acc[i][j][0] = 0u; acc[i][j][1] = 0u; }

    float bsum[8][2], wcv[8][2];
#pragma unroll
    for (int jn = 0; jn < 8; jn++)
#pragma unroll
        for (int e = 0; e < 2; e++) {
            int col = col0 + wn * 64 + jn * 8 + lr * 2 + e;
            bsum[jn][e] = b_Wh[col] + b_We[col] + b_Wg[col] + bh_p[col];
            wcv[jn][e] = Wc[col];
        }

    const int r = tid >> 1, part = (tid & 1) * 16;
    const __half* sa0 = g_cat + (size_t)(row0 + r) * KCAT + 512 + part;
    const __half* sb0 = g_WcatT + (size_t)(col0 + r) * KCAT + 512 + part;
    {
        cp16s(&as[0][r * 40 + part], sa0); cp16s(&as[0][r * 40 + part + 8], sa0 + 8);
        cp16s(&bs[0][r * 40 + part], sb0); cp16s(&bs[0][r * 40 + part + 8], sb0 + 8);
        cp_commit();
    }
    for (int ch = 0; ch < nch; ch++) {
        if (ch < nch - 1) {
            int buf = (ch + 1) & 1;
            const __half* sa = sa0 + (ch + 1) * 32;
            const __half* sb = sb0 + (ch + 1) * 32;
            cp16s(&as[buf][r * 40 + part], sa); cp16s(&as[buf][r * 40 + part + 8], sa + 8);
            cp16s(&bs[buf][r * 40 + part], sb); cp16s(&bs[buf][r * 40 + part + 8], sb + 8);
            cp_commit(); cp_wait<1>();
        } else cp_wait<0>();
        __syncthreads();
        const __half* ab = as[ch & 1];
        const __half* bb2 = bs[ch & 1];
#pragma unroll
        for (int hf2 = 0; hf2 < 2; hf2++) {
            const int kk = hf2 * 16;
            uint32_t ar[2][4];
#pragma unroll
            for (int im = 0; im < 2; im++) {
                const __half* ap = ab + (wm * 32 + im * 16 + lq) * 40 + kk + lr * 2;
                ar[im][0] = ldu32(ap); ar[im][1] = ldu32(ap + 8 * 40);
                ar[im][2] = ldu32(ap + 8); ar[im][3] = ldu32(ap + 8 * 40 + 8);
            }
#pragma unroll
            for (int jn = 0; jn < 8; jn++) {
                const __half* bp = bb2 + (wn * 64 + jn * 8 + lq) * 40 + kk + lr * 2;
                uint32_t b0 = ldu32(bp), b1 = ldu32(bp + 8);
                mma16816h(acc[0][jn], ar[0][0], ar[0][1], ar[0][2], ar[0][3], b0, b1);
                mma16816h(acc[1][jn], ar[1][0], ar[1][1], ar[1][2], ar[1][3], b0, b1);
            }
        }
        __syncthreads();
    }
    // epilogue: add h/x partial from g_hfin, tanh, dot Wc, reduce, atomicAdd
#pragma unroll
    for (int im = 0; im < 2; im++)
#pragma unroll
        for (int hf = 0; hf < 2; hf++) {
            int row = row0 + wm * 32 + im * 16 + lq + hf * 8;
            float rs = 0.f;
#pragma unroll
            for (int jn = 0; jn < 8; jn++) {
                int col = col0 + wn * 64 + jn * 8 + lr * 2;
                float2 hv = __half22float2(*reinterpret_cast<__half2*>(&acc[im][jn][hf]));
                float p0 = g_hfin[(size_t)row * 512 + col];
                float p1 = g_hfin[(size_t)row * 512 + col + 1];
                rs += tanhf(hv.x + p0 + bsum[jn][0]) * wcv[jn][0];
                rs += tanhf(hv.y + p1 + bsum[jn][1]) * wcv[jn][1];
            }
            rs += __shfl_xor_sync(0xffffffffu, rs, 1);
            rs += __shfl_xor_sync(0xffffffffu, rs, 2);
            if (lr == 0) atomicAdd(&g_dot[row], rs);
        }
}

// ---------------- tail elementwise ----------------
__global__ void k_softmax_e() {
    int b = blockIdx.x, tid = threadIdx.x;
    __shared__ float al[MEMN];
    __shared__ float ssum;
    if (tid < MEMN) al[tid] = expf(g_scores[b * MEMN + tid]);
    __syncthreads();
    if (tid == 0) {
        float s = 0.f;
        for (int m = 0; m < MEMN; m++) s += al[m];
        ssum = s;
    }
    __syncthreads();
    float inv = 1.f / ssum;
    for (int hh = tid; hh < Hh; hh += 256) {
        float acc = 0.f;
        for (int m = 0; m < MEMN; m++)
            acc += al[m] * __half2float(g_histB[(size_t)m * (Bb * Hh) + b * Hh + hh]);
        g_cat[(size_t)b * KCAT + 512 + hh] = __float2half(acc * inv);
    }
}

__global__ void k_final2(const float* __restrict__ bc, float* __restrict__ out) {
    int b = blockIdx.x * 256 + threadIdx.x;
    if (b < Bb) out[b] = 1.f / (1.f + expf(-(g_dot[b] + bc[0])));
}

// ---------------- launch ----------------
extern "C" void kernel_launch(void* const* d_in, const int* in_sizes, int n_in,
                              void* d_out, int out_size) {
    const float* X      = (const float*)d_in[0];
    const float* Wh     = (const float*)d_in[1];
    const float* bh_lin = (const float*)d_in[2];
    const float* Wx     = (const float*)d_in[3];
    const float* bx_lin = (const float*)d_in[4];
    const float* Wst    = (const float*)d_in[5];
    const float* bst    = (const float*)d_in[6];
    const float* Ws     = (const float*)d_in[7];
    const float* bs_lin = (const float*)d_in[8];
    const float* bg     = (const float*)d_in[9];
    const float* Waq    = (const float*)d_in[10];
    const float* baq    = (const float*)d_in[11];
    const float* Wah    = (const float*)d_in[12];
    const float* bah    = (const float*)d_in[13];
    const float* vt     = (const float*)d_in[14];
    const float* W_h    = (const float*)d_in[15];
    const float* b_Wh   = (const float*)d_in[16];
    const float* We     = (const float*)d_in[17];
    const float* b_We   = (const float*)d_in[18];
    const float* Wg     = (const float*)d_in[19];
    const float* b_Wg   = (const float*)d_in[20];
    const float* bh_p   = (const float*)d_in[21];
    const float* Wc     = (const float*)d_in[22];
    const float* bc     = (const float*)d_in[23];
    float* out = (float*)d_out;

    cudaFuncSetAttribute(k_recur, cudaFuncAttributeMaxDynamicSharedMemorySize, SM_RECUR);

    k_init<<<(Tt * Bb * (Dd / 2) + 255) / 256, 256>>>(X);
    k_packAll<<<(1376256 + 255) / 256, 256>>>(Wah, Waq, W_h, We, Wg);

    k_recur<<<NCTA, NTHR, SM_RECUR>>>(Wh, Wx, Wst, Ws,
                                      bh_lin, bx_lin, bg, bst, bs_lin);

    // attention + readout
    k_tail1<<<dim3(4, 280), 256>>>(baq, bah, vt);
    k_softmax_e<<<Bb, 256>>>();
    k_catdot<<<dim3(4, 4), 256>>>(b_Wh, b_We, b_Wg, bh_p, Wc);
    k_final2<<<2, 256>>>(bc, out);
}

// round 16
// speedup vs baseline: 1.0306x; 1.0306x over previous
#include <cuda_runtime.h>
#include <cuda_fp16.h>
#include <math.h>
#include <stdint.h>

constexpr int Bb = 512, Tt = 128, Dd = 128, Hh = 512, MEMN = 64;
constexpr int NCTA = 128, NTHR = 256;
constexpr int LD1 = 648, LD2 = 520;          // weight smem row strides (elems, 16B-aligned)
constexpr int SO_W1 = 0;
constexpr int SO_W2 = 96 * LD1 * 2;          // 124416
constexpr int SO_STG = SO_W2 + 80 * LD2 * 2; // 207616
constexpr int STG_BYTES = 128 * 64;          // 8192 per stage (128 rows x 64B, swizzled)
constexpr int SM_RECUR = SO_STG + 3 * STG_BYTES;  // 232192
constexpr int KCAT = 1152;                   // [h 512 | e 512 | x 128]

// ---------------- device scratch ----------------
__device__ __half g_hB[Bb * Hh];                      // h, [b][512]
__device__ __half g_sB[Bb * Hh];                      // s_t, [b][512]
__device__ __half g_Xh[(size_t)Tt * Bb * Dd];         // x, [t][b][128]
__device__ float  g_dtT[Tt * Bb];                     // dt, [t][b]
__device__ __half g_histB[(size_t)MEMN * Bb * Hh];    // [m][b][h]
__device__ __half g_qh[Bb * 2 * Hh];                  // [b][ h | c ]
__device__ __half g_cat[Bb * KCAT];                   // [b][ h | e | x_last ]
__device__ unsigned g_cnt4[128];                      // 4 group counters, 128B apart
__device__ unsigned g_qwdone;
// tail scratch
__device__ __half g_WahT[Hh * Hh];
__device__ __half g_WaqT[Hh * 2 * Hh];
__device__ __half g_WcatT[Hh * KCAT];                 // [n][ W_h k | We k | Wg k ]
__device__ float g_qWf[Bb * Hh];
__device__ float g_hfin[Bb * Hh];
__device__ float g_scores[Bb * MEMN];
__device__ float g_dot[Bb];

// ---------------- helpers ----------------
__device__ __forceinline__ float sigmoidf_(float x) { return 1.f / (1.f + expf(-x)); }

__device__ __forceinline__ uint32_t packh2(float lo, float hi) {
    uint32_t r;
    asm("cvt.rn.f16x2.f32 %0, %1, %2;" : "=r"(r) : "f"(hi), "f"(lo));
    return r;
}
__device__ __forceinline__ uint32_t smem_u32(const void* p) {
    uint32_t a;
    asm("{ .reg .u64 t; cvta.to.shared.u64 t, %1; cvt.u32.u64 %0, t; }" : "=r"(a) : "l"(p));
    return a;
}
__device__ __forceinline__ void cp16b(uint32_t dst, const __half* src) {
    asm volatile("cp.async.cg.shared.global [%0], [%1], 16;" :: "r"(dst), "l"(src));
}
__device__ __forceinline__ void cp16s(__half* dst_smem, const __half* src) {
    uint32_t d = (uint32_t)__cvta_generic_to_shared(dst_smem);
    asm volatile("cp.async.cg.shared.global [%0], [%1], 16;" :: "r"(d), "l"(src));
}
__device__ __forceinline__ void cp_commit() { asm volatile("cp.async.commit_group;"); }
template <int N>
__device__ __forceinline__ void cp_wait() { asm volatile("cp.async.wait_group %0;" :: "n"(N)); }

__device__ __forceinline__ void ldsm4(uint32_t* r, uint32_t a) {
    asm volatile("ldmatrix.sync.aligned.m8n8.x4.shared.b16 {%0,%1,%2,%3}, [%4];"
                 : "=r"(r[0]), "=r"(r[1]), "=r"(r[2]), "=r"(r[3]) : "r"(a));
}
__device__ __forceinline__ void ldsm2(uint32_t* r, uint32_t a) {
    asm volatile("ldmatrix.sync.aligned.m8n8.x2.shared.b16 {%0,%1}, [%2];"
                 : "=r"(r[0]), "=r"(r[1]) : "r"(a));
}
__device__ __forceinline__ uint32_t ldu32(const __half* p) {
    return *reinterpret_cast<const uint32_t*>(p);
}
// f16 accumulate (2 regs)
__device__ __forceinline__ void mma16816h(uint32_t* c, uint32_t a0, uint32_t a1,
                                          uint32_t a2, uint32_t a3, uint32_t b0, uint32_t b1) {
    asm volatile(
        "mma.sync.aligned.m16n8k16.row.col.f16.f16.f16.f16 "
        "{%0,%1}, {%2,%3,%4,%5}, {%6,%7}, {%0,%1};"
        : "+r"(c[0]), "+r"(c[1])
        : "r"(a0), "r"(a1), "r"(a2), "r"(a3), "r"(b0), "r"(b1));
}
// per-group grid barrier (32 CTAs sharing the same mi)
__device__ __forceinline__ void gridbar_g(unsigned* cnt, unsigned target) {
    __syncthreads();
    if (threadIdx.x == 0) {
        __threadfence();
        atomicAdd(cnt, 1u);
        unsigned v;
        do {
            asm volatile("ld.acquire.gpu.u32 %0, [%1];" : "=r"(v) : "l"(cnt) : "memory");
        } while (v < target);
    }
    __syncthreads();
}

// ---------------- init ----------------
__global__ void k_init(const float* __restrict__ X) {
    int idx = blockIdx.x * 256 + threadIdx.x;
    if (idx == 0) g_qwdone = 0u;
    if (idx < 128) g_cnt4[idx] = 0u;
    if (idx < Bb) g_dot[idx] = 0.f;
    if (idx < Bb * MEMN) g_scores[idx] = 0.f;
    if (idx < Bb * Hh) { g_qWf[idx] = 0.f; g_hfin[idx] = 0.f; }
    if (idx < Bb * Hh / 2) reinterpret_cast<uint32_t*>(g_hB)[idx] = 0u;
    if (idx < Tt * Bb) {
        int t = idx >> 9, b = idx & 511;
        g_dtT[idx] = X[((size_t)b * Tt + t) * (Dd + 1) + Dd];
    }
    if (idx < Bb * Dd) {
        int b = idx >> 7, d = idx & 127;
        g_cat[(size_t)b * KCAT + 1024 + d] =
            __float2half(X[((size_t)b * Tt + (Tt - 1)) * (Dd + 1) + d]);
    }
    if (idx < Tt * Bb * (Dd / 2)) {
        int dp = idx & 63, rem = idx >> 6;
        int b = rem & 511, t = rem >> 9;
        const float* xp = X + ((size_t)b * Tt + t) * (Dd + 1) + 2 * dp;
        reinterpret_cast<uint32_t*>(g_Xh)[idx] = packh2(xp[0], xp[1]);
    }
}

// ---------------- merged weight transpose/pack (tail) ----------------
__global__ void k_packAll(const float* __restrict__ Wah, const float* __restrict__ Waq,
                          const float* __restrict__ W_h, const float* __restrict__ We,
                          const float* __restrict__ Wg) {
    int idx = blockIdx.x * 256 + threadIdx.x;
    if (idx < 262144) {
        int n = idx >> 9, k = idx & 511;
        g_WahT[idx] = __float2half(Wah[(size_t)k * 512 + n]);
    } else if (idx < 786432) {
        int j = idx - 262144; int n = j >> 10, k = j & 1023;
        g_WaqT[j] = __float2half(Waq[(size_t)k * 512 + n]);
    } else if (idx < 1376256) {
        int j = idx - 786432;
        int n = j / KCAT, k = j - n * KCAT;
        float v;
        if (k < 512)       v = W_h[(size_t)k * 512 + n];
        else if (k < 1024) v = We[(size_t)(k - 512) * 512 + n];
        else               v = Wg[(size_t)(k - 1024) * 512 + n];
        g_WcatT[j] = __float2half(v);
    }
}

// ---------------- persistent recurrent kernel (R13-proven mainloop) ----------------
__global__ void __launch_bounds__(NTHR, 1)
k_recur(const float* __restrict__ Wh, const float* __restrict__ Wx,
        const float* __restrict__ Wst, const float* __restrict__ Ws,
        const float* __restrict__ bh_lin, const float* __restrict__ bx_lin,
        const float* __restrict__ bg, const float* __restrict__ bst,
        const float* __restrict__ bs_lin) {
    extern __shared__ __align__(16) __half sm[];
    const uint32_t sbase = smem_u32(sm);
    const uint32_t w1u = sbase + SO_W1, w2u = sbase + SO_W2, stgu = sbase + SO_STG;
    __half* w1s = sm;
    __half* w2s = sm + 96 * LD1;

    const int tid = threadIdx.x, cta = blockIdx.x;
    const int w = tid >> 5, lane = tid & 31;
    const int lq = lane >> 2, lr = lane & 3;
    const int wm = w >> 1, wn = w & 1;
    const int mi = cta & 3, hi = cta >> 2;
    const int m0 = mi * 128, hh0 = hi * 16;
    unsigned* cnt = &g_cnt4[mi * 32];

    for (int idx = tid; idx < 96 * 640; idx += NTHR) {
        int n = idx / 640, k = idx - n * 640;
        int wn_ = n / 48, rem = n - wn_ * 48, jn = rem >> 3, c = rem & 7;
        int g = (jn < 5) ? jn + 1 : 0;
        int hh = hh0 + wn_ * 8 + c;
        float v = (k < 512) ? Wh[((size_t)(g * 512 + k)) * 512 + hh]
                            : Wx[((size_t)(g * 128 + (k - 512))) * 512 + hh];
        w1s[n * LD1 + k] = __float2half(v);
    }
    for (int idx = tid; idx < 80 * 512; idx += NTHR) {
        int n = idx >> 9, k = idx & 511;
        int wn_ = n / 40, rem = n - wn_ * 40, jn = rem >> 3, c = rem & 7;
        int hh = hh0 + wn_ * 8 + c;
        w2s[n * LD2 + k] = __float2half(Ws[((size_t)(jn * 512 + k)) * 512 + hh]);
    }
    __syncthreads();

    const int hhp = hh0 + wn * 8 + lr * 2;
    float biasG[5][2], bias0[2], wstv[2];
#pragma unroll
    for (int e = 0; e < 2; e++) {
        int hh = hhp + e;
        bias0[e] = bh_lin[hh] + bx_lin[hh] + bg[hh] + bst[hh];
        wstv[e] = Wst[hh];
#pragma unroll
        for (int q = 0; q < 5; q++) {
            int gc = (q + 1) * 512 + hh;
            biasG[q][e] = bh_lin[gc] + bx_lin[gc] + bg[gc] + bs_lin[q * 512 + hh];
        }
    }

    const int hi4 = (lane >> 4) & 1;
    uint32_t rowA[2], swzA[2];
#pragma unroll
    for (int im = 0; im < 2; im++) {
        int R = wm * 32 + im * 16 + (lane & 15);
        rowA[im] = (uint32_t)R * 64u;
        swzA[im] = (uint32_t)((R >> 1) & 3);
    }
    uint32_t boff1[3];
#pragma unroll
    for (int p = 0; p < 3; p++) {
        int n = wn * 48 + p * 16 + (lane & 7) + ((lane & 16) >> 1);
        boff1[p] = (uint32_t)n * (LD1 * 2) + ((lane & 8) << 1);
    }
    uint32_t boff2[2], boff2x;
#pragma unroll
    for (int p = 0; p < 2; p++) {
        int n = wn * 40 + p * 16 + (lane & 7) + ((lane & 16) >> 1);
        boff2[p] = (uint32_t)n * (LD2 * 2) + ((lane & 8) << 1);
    }
    {
        int n = wn * 40 + 32 + (lane & 7);
        boff2x = (uint32_t)n * (LD2 * 2) + ((lane & 8) << 1);
    }
    const int str = tid >> 1, ss0 = (tid & 1) * 2;
    const uint32_t swr = (uint32_t)((str >> 1) & 3);
    const uint32_t wdst0 = (uint32_t)str * 64u + (((uint32_t)ss0 ^ swr) & 3u) * 16u;
    const uint32_t wdst1 = (uint32_t)str * 64u + (((uint32_t)(ss0 + 1) ^ swr) & 3u) * 16u;

    float c_reg[2][2][2], s_reg[2][2][2];
#pragma unroll
    for (int i = 0; i < 2; i++)
#pragma unroll
        for (int j = 0; j < 2; j++) { c_reg[i][j][0] = 0.f; c_reg[i][j][1] = 0.f; }

    unsigned bar = 0;

    for (int t = 0; t < Tt; t++) {
        uint32_t acc[12][2];
#pragma unroll
        for (int j = 0; j < 12; j++) { acc[j][0] = 0u; acc[j][1] = 0u; }

        // ===== phase 1: [h | x_t] @ W1, K=640, 20 chunks, 3-stage pipe =====
        {
            const __half* hrow = g_hB + (size_t)(m0 + str) * 512 + ss0 * 8;
            const __half* xrow = g_Xh + ((size_t)t * 512 + m0 + str) * 128 + ss0 * 8;
#pragma unroll
            for (int pc = 0; pc < 2; pc++) {
                const __half* src = hrow + pc * 32;
                cp16b(stgu + pc * STG_BYTES + wdst0, src);
                cp16b(stgu + pc * STG_BYTES + wdst1, src + 8);
                cp_commit();
            }
            int st = 0;
            for (int ch = 0; ch < 20; ch++) {
                if (ch < 19) cp_wait<1>(); else cp_wait<0>();
                __syncthreads();
                if (ch + 2 < 20) {
                    int c2 = ch + 2;
                    int s2 = st + 2; if (s2 >= 3) s2 -= 3;
                    const __half* src = (c2 < 16) ? hrow + c2 * 32 : xrow + (c2 - 16) * 32;
                    cp16b(stgu + s2 * STG_BYTES + wdst0, src);
                    cp16b(stgu + s2 * STG_BYTES + wdst1, src + 8);
                    cp_commit();
                }
                const uint32_t abuf = stgu + st * STG_BYTES;
                const uint32_t kb = (uint32_t)ch * 64u;
#pragma unroll
                for (int half = 0; half < 2; half++) {
                    uint32_t A0[4], A1[4], Bv[12];
                    uint32_t sseg = (uint32_t)(half * 2 + hi4);
                    ldsm4(A0, abuf + rowA[0] + ((sseg ^ swzA[0]) & 3u) * 16u);
                    ldsm4(A1, abuf + rowA[1] + ((sseg ^ swzA[1]) & 3u) * 16u);
                    uint32_t kw = kb + (uint32_t)half * 32u;
                    ldsm4(Bv + 0, w1u + boff1[0] + kw);
                    ldsm4(Bv + 4, w1u + boff1[1] + kw);
                    ldsm4(Bv + 8, w1u + boff1[2] + kw);
#pragma unroll
                    for (int jn = 0; jn < 6; jn++) {
                        mma16816h(acc[jn],     A0[0], A0[1], A0[2], A0[3], Bv[2 * jn], Bv[2 * jn + 1]);
                        mma16816h(acc[6 + jn], A1[0], A1[1], A1[2], A1[3], Bv[2 * jn], Bv[2 * jn + 1]);
                    }
                }
                if (++st == 3) st = 0;
            }
        }
#pragma unroll
        for (int im = 0; im < 2; im++)
#pragma unroll
            for (int hf = 0; hf < 2; hf++) {
                int b = m0 + wm * 32 + im * 16 + lq + hf * 8;
                float dt = g_dtT[t * 512 + b];
                float2 pv = __half22float2(*reinterpret_cast<__half2*>(&acc[im * 6 + 5][hf]));
                float s0 = tanhf(pv.x + bias0[0] + dt * wstv[0]);
                float s1 = tanhf(pv.y + bias0[1] + dt * wstv[1]);
                s_reg[im][hf][0] = s0; s_reg[im][hf][1] = s1;
                *reinterpret_cast<uint32_t*>(&g_sB[(size_t)b * 512 + hhp]) = packh2(s0, s1);
            }
        bar += 32; gridbar_g(cnt, bar);

        // ===== phase 2: s @ Ws accumulates onto acc gates, K=512, 16 chunks =====
        {
            const __half* srow = g_sB + (size_t)(m0 + str) * 512 + ss0 * 8;
#pragma unroll
            for (int pc = 0; pc < 2; pc++) {
                const __half* src = srow + pc * 32;
                cp16b(stgu + pc * STG_BYTES + wdst0, src);
                cp16b(stgu + pc * STG_BYTES + wdst1, src + 8);
                cp_commit();
            }
            int st = 0;
            for (int ch = 0; ch < 16; ch++) {
                if (ch < 15) cp_wait<1>(); else cp_wait<0>();
                __syncthreads();
                if (ch + 2 < 16) {
                    int s2 = st + 2; if (s2 >= 3) s2 -= 3;
                    const __half* src = srow + (ch + 2) * 32;
                    cp16b(stgu + s2 * STG_BYTES + wdst0, src);
                    cp16b(stgu + s2 * STG_BYTES + wdst1, src + 8);
                    cp_commit();
                }
                const uint32_t abuf = stgu + st * STG_BYTES;
                const uint32_t kb = (uint32_t)ch * 64u;
#pragma unroll
                for (int half = 0; half < 2; half++) {
                    uint32_t A0[4], A1[4], Bv[10];
                    uint32_t sseg = (uint32_t)(half * 2 + hi4);
                    ldsm4(A0, abuf + rowA[0] + ((sseg ^ swzA[0]) & 3u) * 16u);
                    ldsm4(A1, abuf + rowA[1] + ((sseg ^ swzA[1]) & 3u) * 16u);
                    uint32_t kw = kb + (uint32_t)half * 32u;
                    ldsm4(Bv + 0, w2u + boff2[0] + kw);
                    ldsm4(Bv + 4, w2u + boff2[1] + kw);
                    ldsm2(Bv + 8, w2u + boff2x + kw);
#pragma unroll
                    for (int jn = 0; jn < 5; jn++) {
                        mma16816h(acc[jn],     A0[0], A0[1], A0[2], A0[3], Bv[2 * jn], Bv[2 * jn + 1]);
                        mma16816h(acc[6 + jn], A1[0], A1[1], A1[2], A1[3], Bv[2 * jn], Bv[2 * jn + 1]);
                    }
                }
                if (++st == 3) st = 0;
            }
        }
#pragma unroll
        for (int im = 0; im < 2; im++)
#pragma unroll
            for (int hf = 0; hf < 2; hf++) {
                int b = m0 + wm * 32 + im * 16 + lq + hf * 8;
                float2 gv[5];
#pragma unroll
                for (int q = 0; q < 5; q++)
                    gv[q] = __half22float2(*reinterpret_cast<__half2*>(&acc[im * 6 + q][hf]));
                float h2[2];
#pragma unroll
                for (int e = 0; e < 2; e++) {
                    float p0 = e ? gv[0].y : gv[0].x;
                    float p1 = e ? gv[1].y : gv[1].x;
                    float p2 = e ? gv[2].y : gv[2].x;
                    float p3 = e ? gv[3].y : gv[3].x;
                    float p4 = e ? gv[4].y : gv[4].x;
                    float f  = sigmoidf_(p0 + biasG[0][e]);
                    float i_ = sigmoidf_(p1 + biasG[1][e]);
                    float Tg = sigmoidf_(p2 + biasG[2][e]);
                    float z  = tanhf(p3 + biasG[3][e]);
                    float o  = sigmoidf_(p4 + biasG[4][e]);
                    float cn = f * c_reg[im][hf][e] + i_ * z + Tg * s_reg[im][hf][e];
                    c_reg[im][hf][e] = cn;
                    h2[e] = o * tanhf(cn);
                }
                uint32_t hp2 = packh2(h2[0], h2[1]);
                *reinterpret_cast<uint32_t*>(&g_hB[(size_t)b * 512 + hhp]) = hp2;
                if (t >= Tt - MEMN)
                    *reinterpret_cast<uint32_t*>(
                        &g_histB[(size_t)(t - (Tt - MEMN)) * (Bb * Hh) + (size_t)b * 512 + hhp]) = hp2;
                if (t == Tt - 1) {
                    *reinterpret_cast<uint32_t*>(&g_qh[(size_t)b * 1024 + hhp]) = hp2;
                    *reinterpret_cast<uint32_t*>(&g_qh[(size_t)b * 1024 + 512 + hhp]) =
                        packh2(c_reg[im][hf][0], c_reg[im][hf][1]);
                    *reinterpret_cast<uint32_t*>(&g_cat[(size_t)b * KCAT + hhp]) = hp2;
                }
            }
        bar += 32; gridbar_g(cnt, bar);
    }
}

// ---------------- tail GEMM: qW slices | hsW+scores | cat h/x slices -> hfin ----------------
__global__ void __launch_bounds__(256) k_tail1(const float* __restrict__ baq,
                                               const float* __restrict__ bah,
                                               const float* __restrict__ vt) {
    __shared__ __half as[2][128 * 40];
    __shared__ __half bs[2][128 * 40];
    const int tid = threadIdx.x, w = tid >> 5, lane = tid & 31;
    const int lq = lane >> 2, lr = lane & 3;
    const int wm = w >> 1, wn = w & 1;
    const int col0 = blockIdx.x * 128;

    // mode: 0 = qW slice, 1 = hsW+scores, 2 = cat slice -> hfin
    int mode;
    const __half* A; const __half* Bt; int row0, nch, aStr, bStr; size_t kOff;
    if (blockIdx.y < 16) {
        mode = 0;
        int qi = blockIdx.y;
        row0 = (qi & 3) * 128;
        kOff = (size_t)(qi >> 2) * 256;
        A = g_qh; Bt = g_WaqT; aStr = 1024; bStr = 1024; nch = 8;
    } else if (blockIdx.y < 272) {
        mode = 1;
        row0 = (blockIdx.y - 16) * 128;
        kOff = 0;
        A = g_histB; Bt = g_WahT; aStr = 512; bStr = 512; nch = 16;
    } else if (blockIdx.y < 276) {
        mode = 2;   // cat h-slice
        row0 = (blockIdx.y - 272) * 128;
        kOff = 0;
        A = g_cat; Bt = g_WcatT; aStr = KCAT; bStr = KCAT; nch = 16;
    } else {
        mode = 2;   // cat x-slice
        row0 = (blockIdx.y - 276) * 128;
        kOff = 1024;
        A = g_cat; Bt = g_WcatT; aStr = KCAT; bStr = KCAT; nch = 4;
    }

    uint32_t acc[2][8][2];
#pragma unroll
    for (int i = 0; i < 2; i++)
#pragma unroll
        for (int j = 0; j < 8; j++) { acc[i][j][0] = 0u; acc[i][j][1] = 0u; }

    const int r = tid >> 1, part = (tid & 1) * 16;
    const __half* sa0 = A + (size_t)(row0 + r) * aStr + kOff + part;
    const __half* sb0 = Bt + (size_t)(col0 + r) * bStr + kOff + part;
    {
        cp16s(&as[0][r * 40 + part], sa0); cp16s(&as[0][r * 40 + part + 8], sa0 + 8);
        cp16s(&bs[0][r * 40 + part], sb0); cp16s(&bs[0][r * 40 + part + 8], sb0 + 8);
        cp_commit();
    }
    for (int ch = 0; ch < nch; ch++) {
        if (ch < nch - 1) {
            int buf = (ch + 1) & 1;
            const __half* sa = sa0 + (ch + 1) * 32;
            const __half* sb = sb0 + (ch + 1) * 32;
            cp16s(&as[buf][r * 40 + part], sa); cp16s(&as[buf][r * 40 + part + 8], sa + 8);
            cp16s(&bs[buf][r * 40 + part], sb); cp16s(&bs[buf][r * 40 + part + 8], sb + 8);
            cp_commit(); cp_wait<1>();
        } else cp_wait<0>();
        __syncthreads();
        const __half* ab = as[ch & 1];
        const __half* bb2 = bs[ch & 1];
#pragma unroll
        for (int hf2 = 0; hf2 < 2; hf2++) {
            const int kk = hf2 * 16;
            uint32_t ar[2][4];
#pragma unroll
            for (int im = 0; im < 2; im++) {
                const __half* ap = ab + (wm * 32 + im * 16 + lq) * 40 + kk + lr * 2;
                ar[im][0] = ldu32(ap); ar[im][1] = ldu32(ap + 8 * 40);
                ar[im][2] = ldu32(ap + 8); ar[im][3] = ldu32(ap + 8 * 40 + 8);
            }
#pragma unroll
            for (int jn = 0; jn < 8; jn++) {
                const __half* bp = bb2 + (wn * 64 + jn * 8 + lq) * 40 + kk + lr * 2;
                uint32_t b0 = ldu32(bp), b1 = ldu32(bp + 8);
                mma16816h(acc[0][jn], ar[0][0], ar[0][1], ar[0][2], ar[0][3], b0, b1);
                mma16816h(acc[1][jn], ar[1][0], ar[1][1], ar[1][2], ar[1][3], b0, b1);
            }
        }
        __syncthreads();
    }

    if (mode == 0) {
#pragma unroll
        for (int im = 0; im < 2; im++)
#pragma unroll
            for (int jn = 0; jn < 8; jn++)
#pragma unroll
                for (int hf = 0; hf < 2; hf++) {
                    int row = row0 + wm * 32 + im * 16 + lq + hf * 8;
                    int col = col0 + wn * 64 + jn * 8 + lr * 2;
                    float2 v = __half22float2(*reinterpret_cast<__half2*>(&acc[im][jn][hf]));
                    atomicAdd(&g_qWf[(size_t)row * 512 + col], v.x);
                    atomicAdd(&g_qWf[(size_t)row * 512 + col + 1], v.y);
                }
        __threadfence();
        __syncthreads();
        if (tid == 0) atomicAdd(&g_qwdone, 1u);
    } else if (mode == 2) {
#pragma unroll
        for (int im = 0; im < 2; im++)
#pragma unroll
            for (int jn = 0; jn < 8; jn++)
#pragma unroll
                for (int hf = 0; hf < 2; hf++) {
                    int row = row0 + wm * 32 + im * 16 + lq + hf * 8;
                    int col = col0 + wn * 64 + jn * 8 + lr * 2;
                    float2 v = __half22float2(*reinterpret_cast<__half2*>(&acc[im][jn][hf]));
                    atomicAdd(&g_hfin[(size_t)row * 512 + col], v.x);
                    atomicAdd(&g_hfin[(size_t)row * 512 + col + 1], v.y);
                }
    } else {
        // fused scores epilogue: needs qW complete (64 producer CTAs, all in wave 1)
        float bv[8][2], vv[8][2];
#pragma unroll
        for (int jn = 0; jn < 8; jn++)
#pragma unroll
            for (int e = 0; e < 2; e++) {
                int col = col0 + wn * 64 + jn * 8 + lr * 2 + e;
                bv[jn][e] = baq[col] + bah[col];
                vv[jn][e] = vt[col];
            }
        if (tid == 0) {
            unsigned v;
            do {
                asm volatile("ld.acquire.gpu.u32 %0, [%1];" : "=r"(v) : "l"(&g_qwdone) : "memory");
            } while (v < 64u);
        }
        __syncthreads();
#pragma unroll
        for (int im = 0; im < 2; im++)
#pragma unroll
            for (int hf = 0; hf < 2; hf++) {
                int row = row0 + wm * 32 + im * 16 + lq + hf * 8;
                int b = row & 511, m = row >> 9;
                float rs = 0.f;
#pragma unroll
                for (int jn = 0; jn < 8; jn++) {
                    int col = col0 + wn * 64 + jn * 8 + lr * 2;
                    float2 hv = __half22float2(*reinterpret_cast<__half2*>(&acc[im][jn][hf]));
                    float q0 = g_qWf[(size_t)b * 512 + col];
                    float q1 = g_qWf[(size_t)b * 512 + col + 1];
                    rs += tanhf(hv.x + q0 + bv[jn][0]) * vv[jn][0];
                    rs += tanhf(hv.y + q1 + bv[jn][1]) * vv[jn][1];
                }
                rs += __shfl_xor_sync(0xffffffffu, rs, 1);
                rs += __shfl_xor_sync(0xffffffffu, rs, 2);
                if (lr == 0) atomicAdd(&g_scores[b * MEMN + m], rs);
            }
    }
}

// ---------------- cat GEMM e-slice (K=512) with fused tanh->Wc dot epilogue ----------------
__global__ void __launch_bounds__(256) k_catdot(const float* __restrict__ b_Wh,
                                                const float* __restrict__ b_We,
                                                const float* __restrict__ b_Wg,
                                                const float* __restrict__ bh_p,
                                                const float* __restrict__ Wc) {
    __shared__ __half as[2][128 * 40];
    __shared__ __half bs[2][128 * 40];
    const int tid = threadIdx.x, w = tid >> 5, lane = tid & 31;
    const int lq = lane >> 2, lr = lane & 3;
    const int row0 = blockIdx.y * 128, col0 = blockIdx.x * 128;
    const int wm = w >> 1, wn = w & 1;
    const int nch = 16;   // e-slice K=512

    uint32_t acc[2][8][2];
#pragma unroll
    for (int i = 0; i < 2; i++)
#pragma unroll
        for (int j = 0; j < 8; j++) { acc[i][j][0] = 0u; acc[i][j][1] = 0u; }

    float bsum[8][2], wcv[8][2];
#pragma unroll
    for (int jn = 0; jn < 8; jn++)
#pragma unroll
        for (int e = 0; e < 2; e++) {
            int col = col0 + wn * 64 + jn * 8 + lr * 2 + e;
            bsum[jn][e] = b_Wh[col] + b_We[col] + b_Wg[col] + bh_p[col];
            wcv[jn][e] = Wc[col];
        }

    const int r = tid >> 1, part = (tid & 1) * 16;
    const __half* sa0 = g_cat + (size_t)(row0 + r) * KCAT + 512 + part;
    const __half* sb0 = g_WcatT + (size_t)(col0 + r) * KCAT + 512 + part;
    {
        cp16s(&as[0][r * 40 + part], sa0); cp16s(&as[0][r * 40 + part + 8], sa0 + 8);
        cp16s(&bs[0][r * 40 + part], sb0); cp16s(&bs[0][r * 40 + part + 8], sb0 + 8);
        cp_commit();
    }
    for (int ch = 0; ch < nch; ch++) {
        if (ch < nch - 1) {
            int buf = (ch + 1) & 1;
            const __half* sa = sa0 + (ch + 1) * 32;
            const __half* sb = sb0 + (ch + 1) * 32;
            cp16s(&as[buf][r * 40 + part], sa); cp16s(&as[buf][r * 40 + part + 8], sa + 8);
            cp16s(&bs[buf][r * 40 + part], sb); cp16s(&bs[buf][r * 40 + part + 8], sb + 8);
            cp_commit(); cp_wait<1>();
        } else cp_wait<0>();
        __syncthreads();
        const __half* ab = as[ch & 1];
        const __half* bb2 = bs[ch & 1];
#pragma unroll
        for (int hf2 = 0; hf2 < 2; hf2++) {
            const int kk = hf2 * 16;
            uint32_t ar[2][4];
#pragma unroll
            for (int im = 0; im < 2; im++) {
                const __half* ap = ab + (wm * 32 + im * 16 + lq) * 40 + kk + lr * 2;
                ar[im][0] = ldu32(ap); ar[im][1] = ldu32(ap + 8 * 40);
                ar[im][2] = ldu32(ap + 8); ar[im][3] = ldu32(ap + 8 * 40 + 8);
            }
#pragma unroll
            for (int jn = 0; jn < 8; jn++) {
                const __half* bp = bb2 + (wn * 64 + jn * 8 + lq) * 40 + kk + lr * 2;
                uint32_t b0 = ldu32(bp), b1 = ldu32(bp + 8);
                mma16816h(acc[0][jn], ar[0][0], ar[0][1], ar[0][2], ar[0][3], b0, b1);
                mma16816h(acc[1][jn], ar[1][0], ar[1][1], ar[1][2], ar[1][3], b0, b1);
            }
        }
        __syncthreads();
    }
    // epilogue: add h/x partial from g_hfin, tanh, dot Wc, reduce, atomicAdd
#pragma unroll
    for (int im = 0; im < 2; im++)
#pragma unroll
        for (int hf = 0; hf < 2; hf++) {
            int row = row0 + wm * 32 + im * 16 + lq + hf * 8;
            float rs = 0.f;
#pragma unroll
            for (int jn = 0; jn < 8; jn++) {
                int col = col0 + wn * 64 + jn * 8 + lr * 2;
                float2 hv = __half22float2(*reinterpret_cast<__half2*>(&acc[im][jn][hf]));
                float p0 = g_hfin[(size_t)row * 512 + col];
                float p1 = g_hfin[(size_t)row * 512 + col + 1];
                rs += tanhf(hv.x + p0 + bsum[jn][0]) * wcv[jn][0];
                rs += tanhf(hv.y + p1 + bsum[jn][1]) * wcv[jn][1];
            }
            rs += __shfl_xor_sync(0xffffffffu, rs, 1);
            rs += __shfl_xor_sync(0xffffffffu, rs, 2);
            if (lr == 0) atomicAdd(&g_dot[row], rs);
        }
}

// ---------------- tail elementwise ----------------
__global__ void k_softmax_e() {
    int b = blockIdx.x, tid = threadIdx.x;
    __shared__ float al[MEMN];
    __shared__ float ssum;
    if (tid < MEMN) al[tid] = expf(g_scores[b * MEMN + tid]);
    __syncthreads();
    if (tid == 0) {
        float s = 0.f;
        for (int m = 0; m < MEMN; m++) s += al[m];
        ssum = s;
    }
    __syncthreads();
    float inv = 1.f / ssum;
    for (int hh = tid; hh < Hh; hh += 256) {
        float acc = 0.f;
        for (int m = 0; m < MEMN; m++)
            acc += al[m] * __half2float(g_histB[(size_t)m * (Bb * Hh) + b * Hh + hh]);
        g_cat[(size_t)b * KCAT + 512 + hh] = __float2half(acc * inv);
    }
}

__global__ void k_final2(const float* __restrict__ bc, float* __restrict__ out) {
    int b = blockIdx.x * 256 + threadIdx.x;
    if (b < Bb) out[b] = 1.f / (1.f + expf(-(g_dot[b] + bc[0])));
}

// ---------------- launch ----------------
extern "C" void kernel_launch(void* const* d_in, const int* in_sizes, int n_in,
                              void* d_out, int out_size) {
    const float* X      = (const float*)d_in[0];
    const float* Wh     = (const float*)d_in[1];
    const float* bh_lin = (const float*)d_in[2];
    const float* Wx     = (const float*)d_in[3];
    const float* bx_lin = (const float*)d_in[4];
    const float* Wst    = (const float*)d_in[5];
    const float* bst    = (const float*)d_in[6];
    const float* Ws     = (const float*)d_in[7];
    const float* bs_lin = (const float*)d_in[8];
    const float* bg     = (const float*)d_in[9];
    const float* Waq    = (const float*)d_in[10];
    const float* baq    = (const float*)d_in[11];
    const float* Wah    = (const float*)d_in[12];
    const float* bah    = (const float*)d_in[13];
    const float* vt     = (const float*)d_in[14];
    const float* W_h    = (const float*)d_in[15];
    const float* b_Wh   = (const float*)d_in[16];
    const float* We     = (const float*)d_in[17];
    const float* b_We   = (const float*)d_in[18];
    const float* Wg     = (const float*)d_in[19];
    const float* b_Wg   = (const float*)d_in[20];
    const float* bh_p   = (const float*)d_in[21];
    const float* Wc     = (const float*)d_in[22];
    const float* bc     = (const float*)d_in[23];
    float* out = (float*)d_out;

    cudaFuncSetAttribute(k_recur, cudaFuncAttributeMaxDynamicSharedMemorySize, SM_RECUR);

    k_init<<<(Tt * Bb * (Dd / 2) + 255) / 256, 256>>>(X);
    k_packAll<<<(1376256 + 255) / 256, 256>>>(Wah, Waq, W_h, We, Wg);

    k_recur<<<NCTA, NTHR, SM_RECUR>>>(Wh, Wx, Wst, Ws,
                                      bh_lin, bx_lin, bg, bst, bs_lin);

    // attention + readout
    k_tail1<<<dim3(4, 280), 256>>>(baq, bah, vt);
    k_softmax_e<<<Bb, 256>>>();
    k_catdot<<<dim3(4, 4), 256>>>(b_Wh, b_We, b_Wg, bh_p, Wc);
    k_final2<<<2, 256>>>(bc, out);
}

// round 17
// speedup vs baseline: 1.0356x; 1.0049x over previous
#include <cuda_runtime.h>
#include <cuda_fp16.h>
#include <math.h>
#include <stdint.h>

constexpr int Bb = 512, Tt = 128, Dd = 128, Hh = 512, MEMN = 64;
constexpr int NCTA = 128, NTHR = 256;
constexpr int LD1 = 648, LD2 = 520;          // weight smem row strides (elems, 16B-aligned)
constexpr int SO_W1 = 0;
constexpr int SO_W2 = 96 * LD1 * 2;          // 124416
constexpr int SO_STG = SO_W2 + 80 * LD2 * 2; // 207616
constexpr int STG_BYTES = 128 * 64;          // 8192 per stage (128 rows x 64B, swizzled)
constexpr int SM_RECUR = SO_STG + 3 * STG_BYTES;  // 232192
constexpr int KCAT = 1152;                   // [h 512 | e 512 | x 128]

// ---------------- device scratch ----------------
__device__ __half g_hB[Bb * Hh];                      // h, [b][512]
__device__ __half g_sB[Bb * Hh];                      // s_t, [b][512]
__device__ __half g_Xh[(size_t)Tt * Bb * Dd];         // x, [t][b][128]
__device__ float  g_dtT[Tt * Bb];                     // dt, [t][b]
__device__ __half g_histB[(size_t)MEMN * Bb * Hh];    // [m][b][h]
__device__ __half g_qh[Bb * 2 * Hh];                  // [b][ h | c ]
__device__ __half g_cat[Bb * KCAT];                   // [b][ h | e | x_last ]
__device__ unsigned g_cnt4[128];                      // 4 group counters, 128B apart
__device__ unsigned g_qwdone;
// tail scratch
__device__ __half g_WahT[Hh * Hh];
__device__ __half g_WaqT[Hh * 2 * Hh];
__device__ __half g_WcatT[Hh * KCAT];                 // [n][ W_h k | We k | Wg k ]
__device__ float g_qWf[Bb * Hh];
__device__ float g_hfin[Bb * Hh];
__device__ float g_scores[Bb * MEMN];
__device__ float g_dot[Bb];

// ---------------- helpers ----------------
__device__ __forceinline__ float sigmoidf_(float x) { return 1.f / (1.f + expf(-x)); }

__device__ __forceinline__ uint32_t packh2(float lo, float hi) {
    uint32_t r;
    asm("cvt.rn.f16x2.f32 %0, %1, %2;" : "=r"(r) : "f"(hi), "f"(lo));
    return r;
}
__device__ __forceinline__ uint32_t smem_u32(const void* p) {
    uint32_t a;
    asm("{ .reg .u64 t; cvta.to.shared.u64 t, %1; cvt.u32.u64 %0, t; }" : "=r"(a) : "l"(p));
    return a;
}
__device__ __forceinline__ void cp16b(uint32_t dst, const __half* src) {
    asm volatile("cp.async.cg.shared.global [%0], [%1], 16;" :: "r"(dst), "l"(src));
}
__device__ __forceinline__ void cp16s(__half* dst_smem, const __half* src) {
    uint32_t d = (uint32_t)__cvta_generic_to_shared(dst_smem);
    asm volatile("cp.async.cg.shared.global [%0], [%1], 16;" :: "r"(d), "l"(src));
}
__device__ __forceinline__ void cp_commit() { asm volatile("cp.async.commit_group;"); }
template <int N>
__device__ __forceinline__ void cp_wait() { asm volatile("cp.async.wait_group %0;" :: "n"(N)); }

__device__ __forceinline__ void ldsm4(uint32_t* r, uint32_t a) {
    asm volatile("ldmatrix.sync.aligned.m8n8.x4.shared.b16 {%0,%1,%2,%3}, [%4];"
                 : "=r"(r[0]), "=r"(r[1]), "=r"(r[2]), "=r"(r[3]) : "r"(a));
}
__device__ __forceinline__ void ldsm2(uint32_t* r, uint32_t a) {
    asm volatile("ldmatrix.sync.aligned.m8n8.x2.shared.b16 {%0,%1}, [%2];"
                 : "=r"(r[0]), "=r"(r[1]) : "r"(a));
}
__device__ __forceinline__ uint32_t ldu32(const __half* p) {
    return *reinterpret_cast<const uint32_t*>(p);
}
// f16 accumulate (2 regs)
__device__ __forceinline__ void mma16816h(uint32_t* c, uint32_t a0, uint32_t a1,
                                          uint32_t a2, uint32_t a3, uint32_t b0, uint32_t b1) {
    asm volatile(
        "mma.sync.aligned.m16n8k16.row.col.f16.f16.f16.f16 "
        "{%0,%1}, {%2,%3,%4,%5}, {%6,%7}, {%0,%1};"
        : "+r"(c[0]), "+r"(c[1])
        : "r"(a0), "r"(a1), "r"(a2), "r"(a3), "r"(b0), "r"(b1));
}
// per-group grid barrier (32 CTAs sharing the same mi)
__device__ __forceinline__ void gridbar_g(unsigned* cnt, unsigned target) {
    __syncthreads();
    if (threadIdx.x == 0) {
        __threadfence();
        atomicAdd(cnt, 1u);
        unsigned v;
        do {
            asm volatile("ld.acquire.gpu.u32 %0, [%1];" : "=r"(v) : "l"(cnt) : "memory");
        } while (v < target);
    }
    __syncthreads();
}

// ---------------- merged init + weight pack ----------------
constexpr int INIT_DOM = Tt * Bb * (Dd / 2);   // 4194304
__global__ void k_prep(const float* __restrict__ X,
                       const float* __restrict__ Wah, const float* __restrict__ Waq,
                       const float* __restrict__ W_h, const float* __restrict__ We,
                       const float* __restrict__ Wg) {
    int idx = blockIdx.x * 256 + threadIdx.x;
    if (idx < INIT_DOM) {
        if (idx == 0) g_qwdone = 0u;
        if (idx < 128) g_cnt4[idx] = 0u;
        if (idx < Bb) g_dot[idx] = 0.f;
        if (idx < Bb * MEMN) g_scores[idx] = 0.f;
        if (idx < Bb * Hh) { g_qWf[idx] = 0.f; g_hfin[idx] = 0.f; }
        if (idx < Bb * Hh / 2) reinterpret_cast<uint32_t*>(g_hB)[idx] = 0u;
        if (idx < Tt * Bb) {
            int t = idx >> 9, b = idx & 511;
            g_dtT[idx] = X[((size_t)b * Tt + t) * (Dd + 1) + Dd];
        }
        if (idx < Bb * Dd) {
            int b = idx >> 7, d = idx & 127;
            g_cat[(size_t)b * KCAT + 1024 + d] =
                __float2half(X[((size_t)b * Tt + (Tt - 1)) * (Dd + 1) + d]);
        }
        {
            int dp = idx & 63, rem = idx >> 6;
            int b = rem & 511, t = rem >> 9;
            const float* xp = X + ((size_t)b * Tt + t) * (Dd + 1) + 2 * dp;
            reinterpret_cast<uint32_t*>(g_Xh)[idx] = packh2(xp[0], xp[1]);
        }
    } else {
        int j0 = idx - INIT_DOM;
        if (j0 < 262144) {
            int n = j0 >> 9, k = j0 & 511;
            g_WahT[j0] = __float2half(Wah[(size_t)k * 512 + n]);
        } else if (j0 < 786432) {
            int j = j0 - 262144; int n = j >> 10, k = j & 1023;
            g_WaqT[j] = __float2half(Waq[(size_t)k * 512 + n]);
        } else if (j0 < 1376256) {
            int j = j0 - 786432;
            int n = j / KCAT, k = j - n * KCAT;
            float v;
            if (k < 512)       v = W_h[(size_t)k * 512 + n];
            else if (k < 1024) v = We[(size_t)(k - 512) * 512 + n];
            else               v = Wg[(size_t)(k - 1024) * 512 + n];
            g_WcatT[j] = __float2half(v);
        }
    }
}

// ---------------- persistent recurrent kernel (R13/R15-proven mainloop) ----------------
__global__ void __launch_bounds__(NTHR, 1)
k_recur(const float* __restrict__ Wh, const float* __restrict__ Wx,
        const float* __restrict__ Wst, const float* __restrict__ Ws,
        const float* __restrict__ bh_lin, const float* __restrict__ bx_lin,
        const float* __restrict__ bg, const float* __restrict__ bst,
        const float* __restrict__ bs_lin) {
    extern __shared__ __align__(16) __half sm[];
    const uint32_t sbase = smem_u32(sm);
    const uint32_t w1u = sbase + SO_W1, w2u = sbase + SO_W2, stgu = sbase + SO_STG;
    __half* w1s = sm;
    __half* w2s = sm + 96 * LD1;

    const int tid = threadIdx.x, cta = blockIdx.x;
    const int w = tid >> 5, lane = tid & 31;
    const int lq = lane >> 2, lr = lane & 3;
    const int wm = w >> 1, wn = w & 1;
    const int mi = cta & 3, hi = cta >> 2;
    const int m0 = mi * 128, hh0 = hi * 16;
    unsigned* cnt = &g_cnt4[mi * 32];

    for (int idx = tid; idx < 96 * 640; idx += NTHR) {
        int n = idx / 640, k = idx - n * 640;
        int wn_ = n / 48, rem = n - wn_ * 48, jn = rem >> 3, c = rem & 7;
        int g = (jn < 5) ? jn + 1 : 0;
        int hh = hh0 + wn_ * 8 + c;
        float v = (k < 512) ? Wh[((size_t)(g * 512 + k)) * 512 + hh]
                            : Wx[((size_t)(g * 128 + (k - 512))) * 512 + hh];
        w1s[n * LD1 + k] = __float2half(v);
    }
    for (int idx = tid; idx < 80 * 512; idx += NTHR) {
        int n = idx >> 9, k = idx & 511;
        int wn_ = n / 40, rem = n - wn_ * 40, jn = rem >> 3, c = rem & 7;
        int hh = hh0 + wn_ * 8 + c;
        w2s[n * LD2 + k] = __float2half(Ws[((size_t)(jn * 512 + k)) * 512 + hh]);
    }
    __syncthreads();

    const int hhp = hh0 + wn * 8 + lr * 2;
    float biasG[5][2], bias0[2], wstv[2];
#pragma unroll
    for (int e = 0; e < 2; e++) {
        int hh = hhp + e;
        bias0[e] = bh_lin[hh] + bx_lin[hh] + bg[hh] + bst[hh];
        wstv[e] = Wst[hh];
#pragma unroll
        for (int q = 0; q < 5; q++) {
            int gc = (q + 1) * 512 + hh;
            biasG[q][e] = bh_lin[gc] + bx_lin[gc] + bg[gc] + bs_lin[q * 512 + hh];
        }
    }

    const int hi4 = (lane >> 4) & 1;
    uint32_t rowA[2], swzA[2];
#pragma unroll
    for (int im = 0; im < 2; im++) {
        int R = wm * 32 + im * 16 + (lane & 15);
        rowA[im] = (uint32_t)R * 64u;
        swzA[im] = (uint32_t)((R >> 1) & 3);
    }
    uint32_t boff1[3];
#pragma unroll
    for (int p = 0; p < 3; p++) {
        int n = wn * 48 + p * 16 + (lane & 7) + ((lane & 16) >> 1);
        boff1[p] = (uint32_t)n * (LD1 * 2) + ((lane & 8) << 1);
    }
    uint32_t boff2[2], boff2x;
#pragma unroll
    for (int p = 0; p < 2; p++) {
        int n = wn * 40 + p * 16 + (lane & 7) + ((lane & 16) >> 1);
        boff2[p] = (uint32_t)n * (LD2 * 2) + ((lane & 8) << 1);
    }
    {
        int n = wn * 40 + 32 + (lane & 7);
        boff2x = (uint32_t)n * (LD2 * 2) + ((lane & 8) << 1);
    }
    const int str = tid >> 1, ss0 = (tid & 1) * 2;
    const uint32_t swr = (uint32_t)((str >> 1) & 3);
    const uint32_t wdst0 = (uint32_t)str * 64u + (((uint32_t)ss0 ^ swr) & 3u) * 16u;
    const uint32_t wdst1 = (uint32_t)str * 64u + (((uint32_t)(ss0 + 1) ^ swr) & 3u) * 16u;

    float c_reg[2][2][2], s_reg[2][2][2];
#pragma unroll
    for (int i = 0; i < 2; i++)
#pragma unroll
        for (int j = 0; j < 2; j++) { c_reg[i][j][0] = 0.f; c_reg[i][j][1] = 0.f; }

    unsigned bar = 0;

    for (int t = 0; t < Tt; t++) {
        uint32_t acc[12][2];
#pragma unroll
        for (int j = 0; j < 12; j++) { acc[j][0] = 0u; acc[j][1] = 0u; }

        // ===== phase 1: [h | x_t] @ W1, K=640, 20 chunks, 3-stage pipe =====
        {
            const __half* hrow = g_hB + (size_t)(m0 + str) * 512 + ss0 * 8;
            const __half* xrow = g_Xh + ((size_t)t * 512 + m0 + str) * 128 + ss0 * 8;
#pragma unroll
            for (int pc = 0; pc < 2; pc++) {
                const __half* src = hrow + pc * 32;
                cp16b(stgu + pc * STG_BYTES + wdst0, src);
                cp16b(stgu + pc * STG_BYTES + wdst1, src + 8);
                cp_commit();
            }
            int st = 0;
            for (int ch = 0; ch < 20; ch++) {
                if (ch < 19) cp_wait<1>(); else cp_wait<0>();
                __syncthreads();
                if (ch + 2 < 20) {
                    int c2 = ch + 2;
                    int s2 = st + 2; if (s2 >= 3) s2 -= 3;
                    const __half* src = (c2 < 16) ? hrow + c2 * 32 : xrow + (c2 - 16) * 32;
                    cp16b(stgu + s2 * STG_BYTES + wdst0, src);
                    cp16b(stgu + s2 * STG_BYTES + wdst1, src + 8);
                    cp_commit();
                }
                const uint32_t abuf = stgu + st * STG_BYTES;
                const uint32_t kb = (uint32_t)ch * 64u;
#pragma unroll
                for (int half = 0; half < 2; half++) {
                    uint32_t A0[4], A1[4], Bv[12];
                    uint32_t sseg = (uint32_t)(half * 2 + hi4);
                    ldsm4(A0, abuf + rowA[0] + ((sseg ^ swzA[0]) & 3u) * 16u);
                    ldsm4(A1, abuf + rowA[1] + ((sseg ^ swzA[1]) & 3u) * 16u);
                    uint32_t kw = kb + (uint32_t)half * 32u;
                    ldsm4(Bv + 0, w1u + boff1[0] + kw);
                    ldsm4(Bv + 4, w1u + boff1[1] + kw);
                    ldsm4(Bv + 8, w1u + boff1[2] + kw);
#pragma unroll
                    for (int jn = 0; jn < 6; jn++) {
                        mma16816h(acc[jn],     A0[0], A0[1], A0[2], A0[3], Bv[2 * jn], Bv[2 * jn + 1]);
                        mma16816h(acc[6 + jn], A1[0], A1[1], A1[2], A1[3], Bv[2 * jn], Bv[2 * jn + 1]);
                    }
                }
                if (++st == 3) st = 0;
            }
        }
#pragma unroll
        for (int im = 0; im < 2; im++)
#pragma unroll
            for (int hf = 0; hf < 2; hf++) {
                int b = m0 + wm * 32 + im * 16 + lq + hf * 8;
                float dt = g_dtT[t * 512 + b];
                float2 pv = __half22float2(*reinterpret_cast<__half2*>(&acc[im * 6 + 5][hf]));
                float s0 = tanhf(pv.x + bias0[0] + dt * wstv[0]);
                float s1 = tanhf(pv.y + bias0[1] + dt * wstv[1]);
                s_reg[im][hf][0] = s0; s_reg[im][hf][1] = s1;
                *reinterpret_cast<uint32_t*>(&g_sB[(size_t)b * 512 + hhp]) = packh2(s0, s1);
            }
        bar += 32; gridbar_g(cnt, bar);

        // ===== phase 2: s @ Ws accumulates onto acc gates, K=512, 16 chunks =====
        {
            const __half* srow = g_sB + (size_t)(m0 + str) * 512 + ss0 * 8;
#pragma unroll
            for (int pc = 0; pc < 2; pc++) {
                const __half* src = srow + pc * 32;
                cp16b(stgu + pc * STG_BYTES + wdst0, src);
                cp16b(stgu + pc * STG_BYTES + wdst1, src + 8);
                cp_commit();
            }
            int st = 0;
            for (int ch = 0; ch < 16; ch++) {
                if (ch < 15) cp_wait<1>(); else cp_wait<0>();
                __syncthreads();
                if (ch + 2 < 16) {
                    int s2 = st + 2; if (s2 >= 3) s2 -= 3;
                    const __half* src = srow + (ch + 2) * 32;
                    cp16b(stgu + s2 * STG_BYTES + wdst0, src);
                    cp16b(stgu + s2 * STG_BYTES + wdst1, src + 8);
                    cp_commit();
                }
                const uint32_t abuf = stgu + st * STG_BYTES;
                const uint32_t kb = (uint32_t)ch * 64u;
#pragma unroll
                for (int half = 0; half < 2; half++) {
                    uint32_t A0[4], A1[4], Bv[10];
                    uint32_t sseg = (uint32_t)(half * 2 + hi4);
                    ldsm4(A0, abuf + rowA[0] + ((sseg ^ swzA[0]) & 3u) * 16u);
                    ldsm4(A1, abuf + rowA[1] + ((sseg ^ swzA[1]) & 3u) * 16u);
                    uint32_t kw = kb + (uint32_t)half * 32u;
                    ldsm4(Bv + 0, w2u + boff2[0] + kw);
                    ldsm4(Bv + 4, w2u + boff2[1] + kw);
                    ldsm2(Bv + 8, w2u + boff2x + kw);
#pragma unroll
                    for (int jn = 0; jn < 5; jn++) {
                        mma16816h(acc[jn],     A0[0], A0[1], A0[2], A0[3], Bv[2 * jn], Bv[2 * jn + 1]);
                        mma16816h(acc[6 + jn], A1[0], A1[1], A1[2], A1[3], Bv[2 * jn], Bv[2 * jn + 1]);
                    }
                }
                if (++st == 3) st = 0;
            }
        }
#pragma unroll
        for (int im = 0; im < 2; im++)
#pragma unroll
            for (int hf = 0; hf < 2; hf++) {
                int b = m0 + wm * 32 + im * 16 + lq + hf * 8;
                float2 gv[5];
#pragma unroll
                for (int q = 0; q < 5; q++)
                    gv[q] = __half22float2(*reinterpret_cast<__half2*>(&acc[im * 6 + q][hf]));
                float h2[2];
#pragma unroll
                for (int e = 0; e < 2; e++) {
                    float p0 = e ? gv[0].y : gv[0].x;
                    float p1 = e ? gv[1].y : gv[1].x;
                    float p2 = e ? gv[2].y : gv[2].x;
                    float p3 = e ? gv[3].y : gv[3].x;
                    float p4 = e ? gv[4].y : gv[4].x;
                    float f  = sigmoidf_(p0 + biasG[0][e]);
                    float i_ = sigmoidf_(p1 + biasG[1][e]);
                    float Tg = sigmoidf_(p2 + biasG[2][e]);
                    float z  = tanhf(p3 + biasG[3][e]);
                    float o  = sigmoidf_(p4 + biasG[4][e]);
                    float cn = f * c_reg[im][hf][e] + i_ * z + Tg * s_reg[im][hf][e];
                    c_reg[im][hf][e] = cn;
                    h2[e] = o * tanhf(cn);
                }
                uint32_t hp2 = packh2(h2[0], h2[1]);
                *reinterpret_cast<uint32_t*>(&g_hB[(size_t)b * 512 + hhp]) = hp2;
                if (t >= Tt - MEMN)
                    *reinterpret_cast<uint32_t*>(
                        &g_histB[(size_t)(t - (Tt - MEMN)) * (Bb * Hh) + (size_t)b * 512 + hhp]) = hp2;
                if (t == Tt - 1) {
                    *reinterpret_cast<uint32_t*>(&g_qh[(size_t)b * 1024 + hhp]) = hp2;
                    *reinterpret_cast<uint32_t*>(&g_qh[(size_t)b * 1024 + 512 + hhp]) =
                        packh2(c_reg[im][hf][0], c_reg[im][hf][1]);
                    *reinterpret_cast<uint32_t*>(&g_cat[(size_t)b * KCAT + hhp]) = hp2;
                }
            }
        bar += 32; gridbar_g(cnt, bar);
    }
}

// ---------------- tail GEMM: qW slices | hsW+scores | cat h/x slices -> hfin ----------------
__global__ void __launch_bounds__(256) k_tail1(const float* __restrict__ baq,
                                               const float* __restrict__ bah,
                                               const float* __restrict__ vt) {
    __shared__ __half as[2][128 * 40];
    __shared__ __half bs[2][128 * 40];
    const int tid = threadIdx.x, w = tid >> 5, lane = tid & 31;
    const int lq = lane >> 2, lr = lane & 3;
    const int wm = w >> 1, wn = w & 1;
    const int col0 = blockIdx.x * 128;

    // mode: 0 = qW slice, 1 = hsW+scores, 2 = cat slice -> hfin
    int mode;
    const __half* A; const __half* Bt; int row0, nch, aStr, bStr; size_t kOff;
    if (blockIdx.y < 16) {
        mode = 0;
        int qi = blockIdx.y;
        row0 = (qi & 3) * 128;
        kOff = (size_t)(qi >> 2) * 256;
        A = g_qh; Bt = g_WaqT; aStr = 1024; bStr = 1024; nch = 8;
    } else if (blockIdx.y < 272) {
        mode = 1;
        row0 = (blockIdx.y - 16) * 128;
        kOff = 0;
        A = g_histB; Bt = g_WahT; aStr = 512; bStr = 512; nch = 16;
    } else if (blockIdx.y < 276) {
        mode = 2;   // cat h-slice
        row0 = (blockIdx.y - 272) * 128;
        kOff = 0;
        A = g_cat; Bt = g_WcatT; aStr = KCAT; bStr = KCAT; nch = 16;
    } else {
        mode = 2;   // cat x-slice
        row0 = (blockIdx.y - 276) * 128;
        kOff = 1024;
        A = g_cat; Bt = g_WcatT; aStr = KCAT; bStr = KCAT; nch = 4;
    }

    uint32_t acc[2][8][2];
#pragma unroll
    for (int i = 0; i < 2; i++)
#pragma unroll
        for (int j = 0; j < 8; j++) { acc[i][j][0] = 0u; acc[i][j][1] = 0u; }

    const int r = tid >> 1, part = (tid & 1) * 16;
    const __half* sa0 = A + (size_t)(row0 + r) * aStr + kOff + part;
    const __half* sb0 = Bt + (size_t)(col0 + r) * bStr + kOff + part;
    {
        cp16s(&as[0][r * 40 + part], sa0); cp16s(&as[0][r * 40 + part + 8], sa0 + 8);
        cp16s(&bs[0][r * 40 + part], sb0); cp16s(&bs[0][r * 40 + part + 8], sb0 + 8);
        cp_commit();
    }
    for (int ch = 0; ch < nch; ch++) {
        if (ch < nch - 1) {
            int buf = (ch + 1) & 1;
            const __half* sa = sa0 + (ch + 1) * 32;
            const __half* sb = sb0 + (ch + 1) * 32;
            cp16s(&as[buf][r * 40 + part], sa); cp16s(&as[buf][r * 40 + part + 8], sa + 8);
            cp16s(&bs[buf][r * 40 + part], sb); cp16s(&bs[buf][r * 40 + part + 8], sb + 8);
            cp_commit(); cp_wait<1>();
        } else cp_wait<0>();
        __syncthreads();
        const __half* ab = as[ch & 1];
        const __half* bb2 = bs[ch & 1];
#pragma unroll
        for (int hf2 = 0; hf2 < 2; hf2++) {
            const int kk = hf2 * 16;
            uint32_t ar[2][4];
#pragma unroll
            for (int im = 0; im < 2; im++) {
                const __half* ap = ab + (wm * 32 + im * 16 + lq) * 40 + kk + lr * 2;
                ar[im][0] = ldu32(ap); ar[im][1] = ldu32(ap + 8 * 40);
                ar[im][2] = ldu32(ap + 8); ar[im][3] = ldu32(ap + 8 * 40 + 8);
            }
#pragma unroll
            for (int jn = 0; jn < 8; jn++) {
                const __half* bp = bb2 + (wn * 64 + jn * 8 + lq) * 40 + kk + lr * 2;
                uint32_t b0 = ldu32(bp), b1 = ldu32(bp + 8);
                mma16816h(acc[0][jn], ar[0][0], ar[0][1], ar[0][2], ar[0][3], b0, b1);
                mma16816h(acc[1][jn], ar[1][0], ar[1][1], ar[1][2], ar[1][3], b0, b1);
            }
        }
        __syncthreads();
    }

    if (mode == 0) {
#pragma unroll
        for (int im = 0; im < 2; im++)
#pragma unroll
            for (int jn = 0; jn < 8; jn++)
#pragma unroll
                for (int hf = 0; hf < 2; hf++) {
                    int row = row0 + wm * 32 + im * 16 + lq + hf * 8;
                    int col = col0 + wn * 64 + jn * 8 + lr * 2;
                    float2 v = __half22float2(*reinterpret_cast<__half2*>(&acc[im][jn][hf]));
                    atomicAdd(&g_qWf[(size_t)row * 512 + col], v.x);
                    atomicAdd(&g_qWf[(size_t)row * 512 + col + 1], v.y);
                }
        __threadfence();
        __syncthreads();
        if (tid == 0) atomicAdd(&g_qwdone, 1u);
    } else if (mode == 2) {
#pragma unroll
        for (int im = 0; im < 2; im++)
#pragma unroll
            for (int jn = 0; jn < 8; jn++)
#pragma unroll
                for (int hf = 0; hf < 2; hf++) {
                    int row = row0 + wm * 32 + im * 16 + lq + hf * 8;
                    int col = col0 + wn * 64 + jn * 8 + lr * 2;
                    float2 v = __half22float2(*reinterpret_cast<__half2*>(&acc[im][jn][hf]));
                    atomicAdd(&g_hfin[(size_t)row * 512 + col], v.x);
                    atomicAdd(&g_hfin[(size_t)row * 512 + col + 1], v.y);
                }
    } else {
        // fused scores epilogue: needs qW complete (64 producer CTAs, all in wave 1)
        float bv[8][2], vv[8][2];
#pragma unroll
        for (int jn = 0; jn < 8; jn++)
#pragma unroll
            for (int e = 0; e < 2; e++) {
                int col = col0 + wn * 64 + jn * 8 + lr * 2 + e;
                bv[jn][e] = baq[col] + bah[col];
                vv[jn][e] = vt[col];
            }
        if (tid == 0) {
            unsigned v;
            do {
                asm volatile("ld.acquire.gpu.u32 %0, [%1];" : "=r"(v) : "l"(&g_qwdone) : "memory");
            } while (v < 64u);
        }
        __syncthreads();
#pragma unroll
        for (int im = 0; im < 2; im++)
#pragma unroll
            for (int hf = 0; hf < 2; hf++) {
                int row = row0 + wm * 32 + im * 16 + lq + hf * 8;
                int b = row & 511, m = row >> 9;
                float rs = 0.f;
#pragma unroll
                for (int jn = 0; jn < 8; jn++) {
                    int col = col0 + wn * 64 + jn * 8 + lr * 2;
                    float2 hv = __half22float2(*reinterpret_cast<__half2*>(&acc[im][jn][hf]));
                    float q0 = g_qWf[(size_t)b * 512 + col];
                    float q1 = g_qWf[(size_t)b * 512 + col + 1];
                    rs += tanhf(hv.x + q0 + bv[jn][0]) * vv[jn][0];
                    rs += tanhf(hv.y + q1 + bv[jn][1]) * vv[jn][1];
                }
                rs += __shfl_xor_sync(0xffffffffu, rs, 1);
                rs += __shfl_xor_sync(0xffffffffu, rs, 2);
                if (lr == 0) atomicAdd(&g_scores[b * MEMN + m], rs);
            }
    }
}

// ---------------- cat GEMM e-slice (K=512, 64-row tiles) with fused tanh->Wc dot ----------------
__global__ void __launch_bounds__(256) k_catdot(const float* __restrict__ b_Wh,
                                                const float* __restrict__ b_We,
                                                const float* __restrict__ b_Wg,
                                                const float* __restrict__ bh_p,
                                                const float* __restrict__ Wc) {
    __shared__ __half as[2][64 * 40];
    __shared__ __half bs[2][128 * 40];
    const int tid = threadIdx.x, w = tid >> 5, lane = tid & 31;
    const int lq = lane >> 2, lr = lane & 3;
    const int row0 = blockIdx.y * 64, col0 = blockIdx.x * 128;
    const int wm = w >> 1, wn = w & 1;   // warp: 16 rows x 64 cols
    const int nch = 16;   // e-slice K=512

    uint32_t acc[8][2];
#pragma unroll
    for (int j = 0; j < 8; j++) { acc[j][0] = 0u; acc[j][1] = 0u; }

    float bsum[8][2], wcv[8][2];
#pragma unroll
    for (int jn = 0; jn < 8; jn++)
#pragma unroll
        for (int e = 0; e < 2; e++) {
            int col = col0 + wn * 64 + jn * 8 + lr * 2 + e;
            bsum[jn][e] = b_Wh[col] + b_We[col] + b_Wg[col] + bh_p[col];
            wcv[jn][e] = Wc[col];
        }

    // staging: A rows 64 (2 threads/row over 2 half-rows? use 256 threads: 4 threads/row)
    const int ra = tid >> 2, parta = (tid & 3) * 8;          // A: 64 rows x 32 halves
    const int rb = tid >> 1, partb = (tid & 1) * 16;         // B: 128 rows x 32 halves
    const __half* sa0 = g_cat + (size_t)(row0 + ra) * KCAT + 512 + parta;
    const __half* sb0 = g_WcatT + (size_t)(col0 + rb) * KCAT + 512 + partb;
    {
        cp16s(&as[0][ra * 40 + parta], sa0);
        cp16s(&bs[0][rb * 40 + partb], sb0); cp16s(&bs[0][rb * 40 + partb + 8], sb0 + 8);
        cp_commit();
    }
    for (int ch = 0; ch < nch; ch++) {
        if (ch < nch - 1) {
            int buf = (ch + 1) & 1;
            const __half* sa = sa0 + (ch + 1) * 32;
            const __half* sb = sb0 + (ch + 1) * 32;
            cp16s(&as[buf][ra * 40 + parta], sa);
            cp16s(&bs[buf][rb * 40 + partb], sb); cp16s(&bs[buf][rb * 40 + partb + 8], sb + 8);
            cp_commit(); cp_wait<1>();
        } else cp_wait<0>();
        __syncthreads();
        const __half* ab = as[ch & 1];
        const __half* bb2 = bs[ch & 1];
#pragma unroll
        for (int hf2 = 0; hf2 < 2; hf2++) {
            const int kk = hf2 * 16;
            uint32_t ar[4];
            const __half* ap = ab + (wm * 16 + lq) * 40 + kk + lr * 2;
            ar[0] = ldu32(ap); ar[1] = ldu32(ap + 8 * 40);
            ar[2] = ldu32(ap + 8); ar[3] = ldu32(ap + 8 * 40 + 8);
#pragma unroll
            for (int jn = 0; jn < 8; jn++) {
                const __half* bp = bb2 + (wn * 64 + jn * 8 + lq) * 40 + kk + lr * 2;
                uint32_t b0 = ldu32(bp), b1 = ldu32(bp + 8);
                mma16816h(acc[jn], ar[0], ar[1], ar[2], ar[3], b0, b1);
            }
        }
        __syncthreads();
    }
    // epilogue: add h/x partial from g_hfin, tanh, dot Wc, reduce, atomicAdd
#pragma unroll
    for (int hf = 0; hf < 2; hf++) {
        int row = row0 + wm * 16 + lq + hf * 8;
        float rs = 0.f;
#pragma unroll
        for (int jn = 0; jn < 8; jn++) {
            int col = col0 + wn * 64 + jn * 8 + lr * 2;
            float2 hv = __half22float2(*reinterpret_cast<__half2*>(&acc[jn][hf]));
            float p0 = g_hfin[(size_t)row * 512 + col];
            float p1 = g_hfin[(size_t)row * 512 + col + 1];
            rs += tanhf(hv.x + p0 + bsum[jn][0]) * wcv[jn][0];
            rs += tanhf(hv.y + p1 + bsum[jn][1]) * wcv[jn][1];
        }
        rs += __shfl_xor_sync(0xffffffffu, rs, 1);
        rs += __shfl_xor_sync(0xffffffffu, rs, 2);
        if (lr == 0) atomicAdd(&g_dot[row], rs);
    }
}

// ---------------- tail elementwise ----------------
__global__ void k_softmax_e() {
    int b = blockIdx.x, tid = threadIdx.x;
    __shared__ float al[MEMN];
    __shared__ float ssum;
    if (tid < MEMN) al[tid] = expf(g_scores[b * MEMN + tid]);
    __syncthreads();
    if (tid == 0) {
        float s = 0.f;
        for (int m = 0; m < MEMN; m++) s += al[m];
        ssum = s;
    }
    __syncthreads();
    float inv = 1.f / ssum;
    for (int hh = tid; hh < Hh; hh += 256) {
        float acc = 0.f;
        for (int m = 0; m < MEMN; m++)
            acc += al[m] * __half2float(g_histB[(size_t)m * (Bb * Hh) + b * Hh + hh]);
        g_cat[(size_t)b * KCAT + 512 + hh] = __float2half(acc * inv);
    }
}

__global__ void k_final2(const float* __restrict__ bc, float* __restrict__ out) {
    int b = blockIdx.x * 256 + threadIdx.x;
    if (b < Bb) out[b] = 1.f / (1.f + expf(-(g_dot[b] + bc[0])));
}

// ---------------- launch ----------------
extern "C" void kernel_launch(void* const* d_in, const int* in_sizes, int n_in,
                              void* d_out, int out_size) {
    const float* X      = (const float*)d_in[0];
    const float* Wh     = (const float*)d_in[1];
    const float* bh_lin = (const float*)d_in[2];
    const float* Wx     = (const float*)d_in[3];
    const float* bx_lin = (const float*)d_in[4];
    const float* Wst    = (const float*)d_in[5];
    const float* bst    = (const float*)d_in[6];
    const float* Ws     = (const float*)d_in[7];
    const float* bs_lin = (const float*)d_in[8];
    const float* bg     = (const float*)d_in[9];
    const float* Waq    = (const float*)d_in[10];
    const float* baq    = (const float*)d_in[11];
    const float* Wah    = (const float*)d_in[12];
    const float* bah    = (const float*)d_in[13];
    const float* vt     = (const float*)d_in[14];
    const float* W_h    = (const float*)d_in[15];
    const float* b_Wh   = (const float*)d_in[16];
    const float* We     = (const float*)d_in[17];
    const float* b_We   = (const float*)d_in[18];
    const float* Wg     = (const float*)d_in[19];
    const float* b_Wg   = (const float*)d_in[20];
    const float* bh_p   = (const float*)d_in[21];
    const float* Wc     = (const float*)d_in[22];
    const float* bc     = (const float*)d_in[23];
    float* out = (float*)d_out;

    cudaFuncSetAttribute(k_recur, cudaFuncAttributeMaxDynamicSharedMemorySize, SM_RECUR);

    k_prep<<<(INIT_DOM + 1376256 + 255) / 256, 256>>>(X, Wah, Waq, W_h, We, Wg);

    k_recur<<<NCTA, NTHR, SM_RECUR>>>(Wh, Wx, Wst, Ws,
                                      bh_lin, bx_lin, bg, bst, bs_lin);

    // attention + readout
    k_tail1<<<dim3(4, 280), 256>>>(baq, bah, vt);
    k_softmax_e<<<Bb, 256>>>();
    k_catdot<<<dim3(4, 8), 256>>>(b_Wh, b_We, b_Wg, bh_p, Wc);
    k_final2<<<2, 256>>>(bc, out);
}